// round 7
// baseline (speedup 1.0000x reference)
#include <cuda_runtime.h>
#include <cuda_bf16.h>
#include <math.h>
#include <cstdint>

// Problem dims
constexpr int BB = 64;    // batch
constexpr int TT = 256;   // time steps
constexpr int II = 256;   // input dim
constexpr int HH = 1024;  // hidden
constexpr int CC = 60;    // classes
constexpr int GG = 4096;  // 4*H
constexpr int NCTA = 128; // persistent CTAs; each owns 8 h-cols x 4 gates = 32 gate cols

// Dynamic SMEM layout (lstm_kernel): k128 chunks
constexpr int A_HI = 0;        // 2 bufs x 16KB (64 rows x 128 bf16, row=256B, seg-swizzled)
constexpr int A_LO = 32768;    // 2 bufs x 16KB
constexpr int WF_HI = 65536;   // 64KB fragment-direct W hi
constexpr int WF_LO = 131072;  // 64KB fragment-direct W lo
constexpr int SMEM_DYN = 196608;

// Dynamic SMEM layout (xproj_mma kernel)
constexpr int XA_HI = 0;       // 2 bufs x 16KB (128 rows x 64 bf16, SW128)
constexpr int XA_LO = 32768;   // 2 bufs x 16KB
constexpr int XW_HI = 65536;   // 32KB fragment-direct W_ih hi (64 cols x 256 k)
constexpr int XW_LO = 98304;   // 32KB
constexpr int SMEM_X = 131072;

// Scratch (__device__ globals: allocation-free)
__device__ float g_xproj[(size_t)TT * BB * GG];   // [t][b][g]
__device__ __nv_bfloat16 g_hhi[2][BB * HH];       // h hi, ping-pong
__device__ __nv_bfloat16 g_hlo[2][BB * HH];       // h lo, ping-pong
__device__ __nv_bfloat16 g_xhi[BB * TT * II];     // inputs hi  [(b*T+t)][i]
__device__ __nv_bfloat16 g_xlo[BB * TT * II];
__device__ __nv_bfloat16 g_wihhi[GG * II];        // W_ih hi [g][i]
__device__ __nv_bfloat16 g_wihlo[GG * II];
__device__ unsigned g_bar;                        // single step counter

// ---------------------------------------------------------------------------
// helpers
// ---------------------------------------------------------------------------
__device__ __forceinline__ uint32_t smem_u32(const void* p) {
    uint32_t a;
    asm("{ .reg .u64 t; cvta.to.shared.u64 t, %1; cvt.u32.u64 %0, t; }" : "=r"(a) : "l"(p));
    return a;
}
__device__ __forceinline__ void ldm_x4(uint32_t* r, uint32_t addr) {
    asm volatile("ldmatrix.sync.aligned.m8n8.x4.shared.b16 {%0,%1,%2,%3}, [%4];"
                 : "=r"(r[0]), "=r"(r[1]), "=r"(r[2]), "=r"(r[3]) : "r"(addr));
}
__device__ __forceinline__ void mma_bf16(float* d, const uint32_t* a, uint32_t b0, uint32_t b1) {
    asm volatile(
        "mma.sync.aligned.m16n8k16.row.col.f32.bf16.bf16.f32 "
        "{%0,%1,%2,%3}, {%4,%5,%6,%7}, {%8,%9}, {%0,%1,%2,%3};"
        : "+f"(d[0]), "+f"(d[1]), "+f"(d[2]), "+f"(d[3])
        : "r"(a[0]), "r"(a[1]), "r"(a[2]), "r"(a[3]), "r"(b0), "r"(b1));
}
__device__ __forceinline__ void cp16(uint32_t smem, const void* g) {
    asm volatile("cp.async.cg.shared.global [%0], [%1], 16;" :: "r"(smem), "l"(g));
}
#define CP_COMMIT() asm volatile("cp.async.commit_group;" ::: "memory")
#define CP_WAIT0()  asm volatile("cp.async.wait_group 0;" ::: "memory")

__device__ __forceinline__ uint32_t pack2(__nv_bfloat16 a, __nv_bfloat16 b) {
    return (uint32_t)*(uint16_t*)&a | ((uint32_t)*(uint16_t*)&b << 16);
}
__device__ __forceinline__ float2 unpack2(uint32_t v) {
    __nv_bfloat16 a, b;
    uint16_t x = (uint16_t)v, y = (uint16_t)(v >> 16);
    a = *(__nv_bfloat16*)&x; b = *(__nv_bfloat16*)&y;
    return make_float2(__bfloat162float(a), __bfloat162float(b));
}
__device__ __forceinline__ void poll_ge(const unsigned* p, unsigned tgt) {
    unsigned v;
    do {
        asm volatile("ld.acquire.gpu.global.u32 %0, [%1];" : "=r"(v) : "l"(p) : "memory");
    } while (v < tgt);
}
__device__ __forceinline__ float fsigmoid(float x) {
    return __fdividef(1.f, 1.f + __expf(-x));
}
__device__ __forceinline__ float ftanh(float x) {
    return 1.f - __fdividef(2.f, __expf(2.f * x) + 1.f);
}

// ---------------------------------------------------------------------------
// Zero-init h buffers + step counter.
// ---------------------------------------------------------------------------
__global__ void zero_kernel() {
    int i = blockIdx.x * blockDim.x + threadIdx.x;
    if (i < BB * HH) {
        ((unsigned*)g_hhi)[i] = 0u;
        ((unsigned*)g_hlo)[i] = 0u;
    }
    if (i == 0) g_bar = 0u;
}

// ---------------------------------------------------------------------------
// Convert inputs and W_ih to bf16 hi/lo split (row-major, same layout).
// ---------------------------------------------------------------------------
__global__ void conv_kernel(const float* __restrict__ inp, const float* __restrict__ Wih) {
    int stride = gridDim.x * blockDim.x;
    int i0 = blockIdx.x * blockDim.x + threadIdx.x;
    for (int i = i0; i < 1048576; i += stride) {
        float4 v = ((const float4*)inp)[i];
        __nv_bfloat16 hx = __float2bfloat16(v.x), hy = __float2bfloat16(v.y);
        __nv_bfloat16 hz = __float2bfloat16(v.z), hw = __float2bfloat16(v.w);
        uint2 hi = make_uint2(pack2(hx, hy), pack2(hz, hw));
        uint2 lo = make_uint2(
            pack2(__float2bfloat16(v.x - __bfloat162float(hx)), __float2bfloat16(v.y - __bfloat162float(hy))),
            pack2(__float2bfloat16(v.z - __bfloat162float(hz)), __float2bfloat16(v.w - __bfloat162float(hw))));
        ((uint2*)g_xhi)[i] = hi;
        ((uint2*)g_xlo)[i] = lo;
    }
    for (int i = i0; i < 262144; i += stride) {
        float4 v = ((const float4*)Wih)[i];
        __nv_bfloat16 hx = __float2bfloat16(v.x), hy = __float2bfloat16(v.y);
        __nv_bfloat16 hz = __float2bfloat16(v.z), hw = __float2bfloat16(v.w);
        uint2 hi = make_uint2(pack2(hx, hy), pack2(hz, hw));
        uint2 lo = make_uint2(
            pack2(__float2bfloat16(v.x - __bfloat162float(hx)), __float2bfloat16(v.y - __bfloat162float(hy))),
            pack2(__float2bfloat16(v.z - __bfloat162float(hz)), __float2bfloat16(v.w - __bfloat162float(hw))));
        ((uint2*)g_wihhi)[i] = hi;
        ((uint2*)g_wihlo)[i] = lo;
    }
}

// ---------------------------------------------------------------------------
// x_proj via split-bf16 mma.sync (proven round 4).
// ---------------------------------------------------------------------------
__global__ __launch_bounds__(256, 1) void xproj_mma_kernel(
    const float* __restrict__ bih, const float* __restrict__ bhh) {
    extern __shared__ char sm[];
    const int tid = threadIdx.x;
    const int lane = tid & 31;
    const int w = tid >> 5;
    const int n0 = blockIdx.x * 64;
    const uint32_t smb = smem_u32(sm);

    for (int idx = tid; idx < 8192; idx += 256) {
        int q = idx & 15, ln = (idx >> 4) & 31, ks = idx >> 9;
        int nt = q >> 1, rr = q & 1;
        int nl = nt * 8 + (ln >> 2);
        int k = ks * 16 + rr * 8 + (ln & 3) * 2;
        uint32_t vh = *(const uint32_t*)(g_wihhi + (n0 + nl) * II + k);
        uint32_t vl = *(const uint32_t*)(g_wihlo + (n0 + nl) * II + k);
        ((uint32_t*)(sm + XW_HI))[idx] = vh;
        ((uint32_t*)(sm + XW_LO))[idx] = vl;
    }
    __syncthreads();

    const int grp = lane >> 2, tg = lane & 3;
    float bias0[8], bias1[8];
#pragma unroll
    for (int nt = 0; nt < 8; nt++) {
        int g = n0 + nt * 8 + tg * 2;
        bias0[nt] = bih[g] + bhh[g];
        bias1[nt] = bih[g + 1] + bhh[g + 1];
    }

    const int arow = w * 16 + (lane & 15);
    const int acol = (lane >> 4) * 16;

    for (int miter = 0; miter < 8; miter++) {
        const int m0 = (blockIdx.y * 8 + miter) * 128;

        float acc[8][4];
#pragma unroll
        for (int z = 0; z < 8; z++)
#pragma unroll
            for (int r = 0; r < 4; r++) acc[z][r] = 0.f;

#pragma unroll
        for (int i = 0; i < 4; i++) {
            int s = i * 256 + tid;
            int row = s >> 3, sb = s & 7;
            int gidx = (m0 + row) * 32 + sb;
            uint4 vh = ((const uint4*)g_xhi)[gidx];
            uint4 vl = ((const uint4*)g_xlo)[gidx];
            int off = row * 128 + sb * 16;
            int sw = off ^ ((off >> 3) & 0x70);
            *(uint4*)(sm + XA_HI + sw) = vh;
            *(uint4*)(sm + XA_LO + sw) = vl;
        }
        __syncthreads();

        for (int ch = 0; ch < 4; ch++) {
            const int buf = ch & 1;
            uint4 ph[4], pl[4];
            if (ch < 3) {
#pragma unroll
                for (int i = 0; i < 4; i++) {
                    int s = i * 256 + tid;
                    int row = s >> 3, sb = s & 7;
                    int gidx = (m0 + row) * 32 + (ch + 1) * 8 + sb;
                    ph[i] = ((const uint4*)g_xhi)[gidx];
                    pl[i] = ((const uint4*)g_xlo)[gidx];
                }
            }
            const uint32_t abh = smb + XA_HI + buf * 16384;
            const uint32_t abl = smb + XA_LO + buf * 16384;
#pragma unroll
            for (int kl = 0; kl < 4; kl++) {
                const int ks = ch * 4 + kl;
                int off = arow * 128 + kl * 32 + acol;
                int sw = off ^ ((off >> 3) & 0x70);
                uint32_t ah[4], al[4];
                ldm_x4(ah, abh + sw);
                ldm_x4(al, abl + sw);
                const uint4* wh4 = (const uint4*)(sm + XW_HI) + (ks * 32 + lane) * 4;
                const uint4* wl4 = (const uint4*)(sm + XW_LO) + (ks * 32 + lane) * 4;
#pragma unroll
                for (int q4 = 0; q4 < 4; q4++) {
                    uint4 bh = wh4[q4];
                    uint4 bl = wl4[q4];
                    mma_bf16(acc[2 * q4], ah, bh.x, bh.y);
                    mma_bf16(acc[2 * q4 + 1], ah, bh.z, bh.w);
                    mma_bf16(acc[2 * q4], al, bh.x, bh.y);
                    mma_bf16(acc[2 * q4 + 1], al, bh.z, bh.w);
                    mma_bf16(acc[2 * q4], ah, bl.x, bl.y);
                    mma_bf16(acc[2 * q4 + 1], ah, bl.z, bl.w);
                }
            }
            if (ch < 3) {
                char* dh = sm + XA_HI + (buf ^ 1) * 16384;
                char* dl = sm + XA_LO + (buf ^ 1) * 16384;
#pragma unroll
                for (int i = 0; i < 4; i++) {
                    int s = i * 256 + tid;
                    int row = s >> 3, sb = s & 7;
                    int off = row * 128 + sb * 16;
                    int sw = off ^ ((off >> 3) & 0x70);
                    *(uint4*)(dh + sw) = ph[i];
                    *(uint4*)(dl + sw) = pl[i];
                }
            }
            __syncthreads();
        }

        int r0 = m0 + w * 16 + grp;
        int r1 = r0 + 8;
        size_t ob0 = ((size_t)(r0 & 255) * BB + (r0 >> 8)) * GG;
        size_t ob1 = ((size_t)(r1 & 255) * BB + (r1 >> 8)) * GG;
#pragma unroll
        for (int nt = 0; nt < 8; nt++) {
            int g = n0 + nt * 8 + tg * 2;
            float2 v0 = make_float2(acc[nt][0] + bias0[nt], acc[nt][1] + bias1[nt]);
            float2 v1 = make_float2(acc[nt][2] + bias0[nt], acc[nt][3] + bias1[nt]);
            *(float2*)&g_xproj[ob0 + g] = v0;
            *(float2*)&g_xproj[ob1 + g] = v1;
        }
    }
}

// ---------------------------------------------------------------------------
// Persistent LSTM recurrence: 128 CTAs x 256 thr, mma.sync bf16 3-term split.
// R5 structure (k128 chunks x 8, one syncthreads per chunk) + split
// accumulators (acc_h / acc_l) + cp.async staging + single step counter.
// ---------------------------------------------------------------------------
__global__ __launch_bounds__(256, 1) void lstm_kernel(const float* __restrict__ Whh) {
    extern __shared__ char sm[];
    const int tid = threadIdx.x;
    const int lane = tid & 31;
    const int w = tid >> 5;
    const int mt = w & 3, nh = w >> 2;
    const int hc0 = blockIdx.x * 8;
    const uint32_t smb = smem_u32(sm);

    // ---- one-time: W fragment fill (hi/lo split, fragment-direct layout) ----
    for (int idx = tid; idx < 16384; idx += 256) {
        int r = idx & 3, ln = (idx >> 2) & 31, ks = (idx >> 7) & 63, nhh = idx >> 13;
        int nt = r >> 1;
        int kk = (r & 1) * 8 + (ln & 3) * 2;
        int nl = nhh * 16 + nt * 8 + (ln >> 2);
        int k = ks * 16 + kk;
        int gr = (nl >> 3) * 1024 + hc0 + (nl & 7);
        float w0 = Whh[gr * 1024 + k];
        float w1 = Whh[gr * 1024 + k + 1];
        __nv_bfloat16 h0 = __float2bfloat16(w0), h1 = __float2bfloat16(w1);
        __nv_bfloat16 l0 = __float2bfloat16(w0 - __bfloat162float(h0));
        __nv_bfloat16 l1 = __float2bfloat16(w1 - __bfloat162float(h1));
        ((uint32_t*)(sm + WF_HI))[idx] = pack2(h0, h1);
        ((uint32_t*)(sm + WF_LO))[idx] = pack2(l0, l1);
    }
    __syncthreads();

    // staging constants: thread handles 4 x 16B segments per half per chunk
    int ssw[4], sgix[4];
#pragma unroll
    for (int i = 0; i < 4; i++) {
        int s = i * 256 + tid;
        int row = s >> 4, seg = s & 15;
        ssw[i] = row * 256 + ((seg ^ (row & 7)) << 4);
        sgix[i] = row * 128 + seg;          // + ch*16 per chunk (uint4 units)
    }

    // A ldmatrix per-lane constants (row = arow, seg swizzled per row)
    const int arow = mt * 16 + (lane & 15);
    const int ahalf = lane >> 4;            // k-half within kstep

    // epilogue ownership: this thread handles states (b, ej) and (b, ej+4)
    const int eb = tid & 63, ej = tid >> 6;
    float c0 = 0.f, c1 = 0.f;

    for (int t = 0; t < TT; t++) {
        const uint4* ghi = (const uint4*)g_hhi[t & 1];
        const uint4* glo = (const uint4*)g_hlo[t & 1];
        const float* xg = g_xproj + (size_t)t * BB * GG;

        // wait for all CTAs to have finished step t-1
        if (t) {
            if (lane == 0) poll_ge(&g_bar, (unsigned)NCTA * t);
            __syncwarp();
        }

        // prefetch this thread's xproj values (4 gates x 2 states)
        float xp[8];
#pragma unroll
        for (int q = 0; q < 4; q++) {
            xp[q] = xg[(size_t)eb * GG + q * HH + hc0 + ej];
            xp[4 + q] = xg[(size_t)eb * GG + q * HH + hc0 + ej + 4];
        }

        float acc_h[2][4], acc_l[2][4];
#pragma unroll
        for (int z = 0; z < 2; z++)
#pragma unroll
            for (int r = 0; r < 4; r++) { acc_h[z][r] = 0.f; acc_l[z][r] = 0.f; }

        // prologue: stage chunk 0 -> buf 0 via cp.async
#pragma unroll
        for (int i = 0; i < 4; i++) {
            cp16(smb + A_HI + ssw[i], ghi + sgix[i]);
            cp16(smb + A_LO + ssw[i], glo + sgix[i]);
        }
        CP_COMMIT();
        CP_WAIT0();
        __syncthreads();

        for (int ch = 0; ch < 8; ch++) {
            const int buf = ch & 1;
            if (ch < 7) {
                const uint32_t dsth = smb + A_HI + (buf ^ 1) * 16384;
                const uint32_t dstl = smb + A_LO + (buf ^ 1) * 16384;
#pragma unroll
                for (int i = 0; i < 4; i++) {
                    cp16(dsth + ssw[i], ghi + sgix[i] + (ch + 1) * 16);
                    cp16(dstl + ssw[i], glo + sgix[i] + (ch + 1) * 16);
                }
                CP_COMMIT();
            }
            const uint32_t abh = smb + A_HI + buf * 16384;
            const uint32_t abl = smb + A_LO + buf * 16384;
            const uint4* wfh = (const uint4*)(sm + WF_HI) + ((nh * 64 + ch * 8) * 32 + lane);
            const uint4* wfl = (const uint4*)(sm + WF_LO) + ((nh * 64 + ch * 8) * 32 + lane);
#pragma unroll
            for (int kl = 0; kl < 8; kl++) {
                int seg = kl * 2 + ahalf;
                int sw = arow * 256 + ((seg ^ (arow & 7)) << 4);
                uint32_t ah[4], al[4];
                ldm_x4(ah, abh + sw);
                ldm_x4(al, abl + sw);
                uint4 bh = wfh[kl * 32];
                uint4 bl = wfl[kl * 32];
                mma_bf16(acc_h[0], ah, bh.x, bh.y);     // chain 1
                mma_bf16(acc_h[1], ah, bh.z, bh.w);     // chain 2
                mma_bf16(acc_l[0], al, bh.x, bh.y);     // chain 3
                mma_bf16(acc_l[1], al, bh.z, bh.w);     // chain 4
                mma_bf16(acc_l[0], ah, bl.x, bl.y);     // chain 3
                mma_bf16(acc_l[1], ah, bl.z, bl.w);     // chain 4
            }
            if (ch < 7) CP_WAIT0();
            __syncthreads();
        }

        // epilogue: exchange D fragments via SMEM [32 cols][stride 72]
        float* sg = (float*)sm;
        {
            int grp = lane >> 2, tg = lane & 3;
#pragma unroll
            for (int nt = 0; nt < 2; nt++) {
                int col = nh * 16 + nt * 8 + tg * 2;
                int row = mt * 16 + grp;
                sg[col * 72 + row] = acc_h[nt][0] + acc_l[nt][0];
                sg[(col + 1) * 72 + row] = acc_h[nt][1] + acc_l[nt][1];
                sg[col * 72 + row + 8] = acc_h[nt][2] + acc_l[nt][2];
                sg[(col + 1) * 72 + row + 8] = acc_h[nt][3] + acc_l[nt][3];
            }
        }
        __syncthreads();

        // pointwise update (fast math): 512 states over 256 threads (2 each)
        {
            __nv_bfloat16* hh = g_hhi[(t + 1) & 1];
            __nv_bfloat16* hl = g_hlo[(t + 1) & 1];
            {
                float iv = sg[(0 + ej) * 72 + eb] + xp[0];
                float fv = sg[(8 + ej) * 72 + eb] + xp[1];
                float gv = sg[(16 + ej) * 72 + eb] + xp[2];
                float ov = sg[(24 + ej) * 72 + eb] + xp[3];
                float cn = fsigmoid(fv) * c0 + fsigmoid(iv) * ftanh(gv);
                c0 = cn;
                float hn = fsigmoid(ov) * ftanh(cn);
                __nv_bfloat16 hbb = __float2bfloat16(hn);
                hh[eb * HH + hc0 + ej] = hbb;
                hl[eb * HH + hc0 + ej] = __float2bfloat16(hn - __bfloat162float(hbb));
            }
            {
                int j = ej + 4;
                float iv = sg[(0 + j) * 72 + eb] + xp[4];
                float fv = sg[(8 + j) * 72 + eb] + xp[5];
                float gv = sg[(16 + j) * 72 + eb] + xp[6];
                float ov = sg[(24 + j) * 72 + eb] + xp[7];
                float cn = fsigmoid(fv) * c1 + fsigmoid(iv) * ftanh(gv);
                c1 = cn;
                float hn = fsigmoid(ov) * ftanh(cn);
                __nv_bfloat16 hbb = __float2bfloat16(hn);
                hh[eb * HH + hc0 + j] = hbb;
                hl[eb * HH + hc0 + j] = __float2bfloat16(hn - __bfloat162float(hbb));
            }
        }
        __threadfence();
        __syncthreads();
        if (tid == 0) atomicAdd(&g_bar, 1u);
    }
}

// ---------------------------------------------------------------------------
// logits = h_last @ fc_w^T + fc_b; out = log_softmax.  grid=64, block=256.
// ---------------------------------------------------------------------------
__global__ __launch_bounds__(256) void fc_kernel(const float* __restrict__ fcw,
                                                 const float* __restrict__ fcb,
                                                 float* __restrict__ out) {
    __shared__ float sh[HH];
    __shared__ float sl[64];
    __shared__ float s_red[2];
    int b = blockIdx.x;
    int tid = threadIdx.x;
    int w = tid >> 5, lane = tid & 31;

    {
        uint2 vh = ((const uint2*)(g_hhi[0] + b * HH))[tid];
        uint2 vl = ((const uint2*)(g_hlo[0] + b * HH))[tid];
        float2 h0 = unpack2(vh.x), h1 = unpack2(vh.y);
        float2 l0 = unpack2(vl.x), l1 = unpack2(vl.y);
        float4 f = make_float4(h0.x + l0.x, h0.y + l0.y, h1.x + l1.x, h1.y + l1.y);
        ((float4*)sh)[tid] = f;
    }
    __syncthreads();

#pragma unroll
    for (int cc = 0; cc < 8; cc++) {
        int c = w * 8 + cc;
        float s = 0.f;
        if (c < CC) {
            const float* wr = fcw + c * HH;
#pragma unroll 8
            for (int i = 0; i < 32; i++) {
                int k = i * 32 + lane;
                s += sh[k] * wr[k];
            }
        }
#pragma unroll
        for (int off = 16; off > 0; off >>= 1) s += __shfl_xor_sync(0xFFFFFFFF, s, off);
        if (lane == 0) sl[c] = (c < CC) ? s + fcb[c] : -1e30f;
    }
    __syncthreads();

    if (w == 0) {
        float v0 = sl[lane], v1 = sl[lane + 32];
        float m = fmaxf(v0, v1);
#pragma unroll
        for (int off = 16; off > 0; off >>= 1) m = fmaxf(m, __shfl_xor_sync(0xFFFFFFFF, m, off));
        float e = expf(v0 - m) + expf(v1 - m);
#pragma unroll
        for (int off = 16; off > 0; off >>= 1) e += __shfl_xor_sync(0xFFFFFFFF, e, off);
        if (lane == 0) { s_red[0] = m; s_red[1] = logf(e); }
    }
    __syncthreads();
    if (tid < CC) out[b * CC + tid] = sl[tid] - s_red[0] - s_red[1];
}

// ---------------------------------------------------------------------------
extern "C" void kernel_launch(void* const* d_in, const int* in_sizes, int n_in,
                              void* d_out, int out_size) {
    const float* inp = (const float*)d_in[0];   // [B,T,I]
    const float* Wih = (const float*)d_in[1];   // [4H,I]
    const float* Whh = (const float*)d_in[2];   // [4H,H]
    const float* bih = (const float*)d_in[3];   // [4H]
    const float* bhh = (const float*)d_in[4];   // [4H]
    const float* fcw = (const float*)d_in[5];   // [C,H]
    const float* fcb = (const float*)d_in[6];   // [C]
    float* out = (float*)d_out;                 // [B,C]

    cudaFuncSetAttribute(lstm_kernel, cudaFuncAttributeMaxDynamicSharedMemorySize, SMEM_DYN);
    cudaFuncSetAttribute(xproj_mma_kernel, cudaFuncAttributeMaxDynamicSharedMemorySize, SMEM_X);

    zero_kernel<<<512, 256>>>();
    conv_kernel<<<1024, 256>>>(inp, Wih);

    dim3 gx(64, 16);
    xproj_mma_kernel<<<gx, 256, SMEM_X>>>(bih, bhh);

    lstm_kernel<<<NCTA, 256, SMEM_DYN>>>(Whh);

    fc_kernel<<<BB, 64 * 4>>>(fcw, fcb, out);
}

// round 8
// speedup vs baseline: 1.5072x; 1.5072x over previous
#include <cuda_runtime.h>
#include <cuda_bf16.h>
#include <cuda_fp16.h>
#include <math.h>
#include <cstdint>

// Problem dims
constexpr int BB = 64;    // batch
constexpr int TT = 256;   // time steps
constexpr int II = 256;   // input dim
constexpr int HH = 1024;  // hidden
constexpr int CC = 60;    // classes
constexpr int GG = 4096;  // 4*H
constexpr int NCTA = 128; // persistent CTAs; each owns 8 h-cols x 4 gates = 32 gate cols

// Dynamic SMEM layout (lstm_kernel): k128 chunks, fp16 2-term
constexpr int A_HI = 0;        // 2 bufs x 16KB (64 rows x 128 fp16, row=256B, seg-swizzled)
constexpr int A_LO = 32768;    // 2 bufs x 16KB
constexpr int WF = 65536;      // 64KB fragment-direct W (fp16)
constexpr int SMEM_DYN = 131072;

// Dynamic SMEM layout (xproj_mma kernel)
constexpr int XA_HI = 0;       // 2 bufs x 16KB (128 rows x 64 bf16, SW128)
constexpr int XA_LO = 32768;   // 2 bufs x 16KB
constexpr int XW_HI = 65536;   // 32KB fragment-direct W_ih hi (64 cols x 256 k)
constexpr int XW_LO = 98304;   // 32KB
constexpr int SMEM_X = 131072;

// Scratch (__device__ globals: allocation-free)
__device__ float g_xproj[(size_t)TT * BB * GG];   // [t][b][g]
__device__ __half g_hhi[2][BB * HH];              // h hi (fp16), ping-pong
__device__ __half g_hlo[2][BB * HH];              // h lo (fp16), ping-pong
__device__ __nv_bfloat16 g_xhi[BB * TT * II];     // inputs hi  [(b*T+t)][i]
__device__ __nv_bfloat16 g_xlo[BB * TT * II];
__device__ __nv_bfloat16 g_wihhi[GG * II];        // W_ih hi [g][i]
__device__ __nv_bfloat16 g_wihlo[GG * II];
__device__ unsigned g_cnt[8];                     // per-column-group step counters

// ---------------------------------------------------------------------------
// helpers
// ---------------------------------------------------------------------------
__device__ __forceinline__ uint32_t smem_u32(const void* p) {
    uint32_t a;
    asm("{ .reg .u64 t; cvta.to.shared.u64 t, %1; cvt.u32.u64 %0, t; }" : "=r"(a) : "l"(p));
    return a;
}
__device__ __forceinline__ void ldm_x4(uint32_t* r, uint32_t addr) {
    asm volatile("ldmatrix.sync.aligned.m8n8.x4.shared.b16 {%0,%1,%2,%3}, [%4];"
                 : "=r"(r[0]), "=r"(r[1]), "=r"(r[2]), "=r"(r[3]) : "r"(addr));
}
__device__ __forceinline__ void mma_bf16(float* d, const uint32_t* a, uint32_t b0, uint32_t b1) {
    asm volatile(
        "mma.sync.aligned.m16n8k16.row.col.f32.bf16.bf16.f32 "
        "{%0,%1,%2,%3}, {%4,%5,%6,%7}, {%8,%9}, {%0,%1,%2,%3};"
        : "+f"(d[0]), "+f"(d[1]), "+f"(d[2]), "+f"(d[3])
        : "r"(a[0]), "r"(a[1]), "r"(a[2]), "r"(a[3]), "r"(b0), "r"(b1));
}
__device__ __forceinline__ void mma_f16(float* d, const uint32_t* a, uint32_t b0, uint32_t b1) {
    asm volatile(
        "mma.sync.aligned.m16n8k16.row.col.f32.f16.f16.f32 "
        "{%0,%1,%2,%3}, {%4,%5,%6,%7}, {%8,%9}, {%0,%1,%2,%3};"
        : "+f"(d[0]), "+f"(d[1]), "+f"(d[2]), "+f"(d[3])
        : "r"(a[0]), "r"(a[1]), "r"(a[2]), "r"(a[3]), "r"(b0), "r"(b1));
}
__device__ __forceinline__ uint32_t pack2(__nv_bfloat16 a, __nv_bfloat16 b) {
    return (uint32_t)*(uint16_t*)&a | ((uint32_t)*(uint16_t*)&b << 16);
}
__device__ __forceinline__ uint32_t pack2h(__half a, __half b) {
    return (uint32_t)*(uint16_t*)&a | ((uint32_t)*(uint16_t*)&b << 16);
}
__device__ __forceinline__ float2 unpack2h(uint32_t v) {
    __half2 h = *(__half2*)&v;
    return __half22float2(h);
}
__device__ __forceinline__ void poll_ge(const unsigned* p, unsigned tgt) {
    unsigned v;
    do {
        asm volatile("ld.acquire.gpu.global.u32 %0, [%1];" : "=r"(v) : "l"(p) : "memory");
    } while (v < tgt);
}
__device__ __forceinline__ float fsigmoid(float x) {
    return __fdividef(1.f, 1.f + __expf(-x));
}
__device__ __forceinline__ float ftanh(float x) {
    return 1.f - __fdividef(2.f, __expf(2.f * x) + 1.f);
}

// ---------------------------------------------------------------------------
// Zero-init h buffers + group counters.
// ---------------------------------------------------------------------------
__global__ void zero_kernel() {
    int i = blockIdx.x * blockDim.x + threadIdx.x;
    if (i < BB * HH) {            // u32 words cover both ping-pong buffers
        ((unsigned*)g_hhi)[i] = 0u;
        ((unsigned*)g_hlo)[i] = 0u;
    }
    if (i < 8) g_cnt[i] = 0u;
}

// ---------------------------------------------------------------------------
// Convert inputs and W_ih to bf16 hi/lo split (row-major, same layout).
// ---------------------------------------------------------------------------
__global__ void conv_kernel(const float* __restrict__ inp, const float* __restrict__ Wih) {
    int stride = gridDim.x * blockDim.x;
    int i0 = blockIdx.x * blockDim.x + threadIdx.x;
    for (int i = i0; i < 1048576; i += stride) {
        float4 v = ((const float4*)inp)[i];
        __nv_bfloat16 hx = __float2bfloat16(v.x), hy = __float2bfloat16(v.y);
        __nv_bfloat16 hz = __float2bfloat16(v.z), hw = __float2bfloat16(v.w);
        uint2 hi = make_uint2(pack2(hx, hy), pack2(hz, hw));
        uint2 lo = make_uint2(
            pack2(__float2bfloat16(v.x - __bfloat162float(hx)), __float2bfloat16(v.y - __bfloat162float(hy))),
            pack2(__float2bfloat16(v.z - __bfloat162float(hz)), __float2bfloat16(v.w - __bfloat162float(hw))));
        ((uint2*)g_xhi)[i] = hi;
        ((uint2*)g_xlo)[i] = lo;
    }
    for (int i = i0; i < 262144; i += stride) {
        float4 v = ((const float4*)Wih)[i];
        __nv_bfloat16 hx = __float2bfloat16(v.x), hy = __float2bfloat16(v.y);
        __nv_bfloat16 hz = __float2bfloat16(v.z), hw = __float2bfloat16(v.w);
        uint2 hi = make_uint2(pack2(hx, hy), pack2(hz, hw));
        uint2 lo = make_uint2(
            pack2(__float2bfloat16(v.x - __bfloat162float(hx)), __float2bfloat16(v.y - __bfloat162float(hy))),
            pack2(__float2bfloat16(v.z - __bfloat162float(hz)), __float2bfloat16(v.w - __bfloat162float(hw))));
        ((uint2*)g_wihhi)[i] = hi;
        ((uint2*)g_wihlo)[i] = lo;
    }
}

// ---------------------------------------------------------------------------
// x_proj via split-bf16 mma.sync (proven round 4).
// ---------------------------------------------------------------------------
__global__ __launch_bounds__(256, 1) void xproj_mma_kernel(
    const float* __restrict__ bih, const float* __restrict__ bhh) {
    extern __shared__ char sm[];
    const int tid = threadIdx.x;
    const int lane = tid & 31;
    const int w = tid >> 5;
    const int n0 = blockIdx.x * 64;
    const uint32_t smb = smem_u32(sm);

    for (int idx = tid; idx < 8192; idx += 256) {
        int q = idx & 15, ln = (idx >> 4) & 31, ks = idx >> 9;
        int nt = q >> 1, rr = q & 1;
        int nl = nt * 8 + (ln >> 2);
        int k = ks * 16 + rr * 8 + (ln & 3) * 2;
        uint32_t vh = *(const uint32_t*)(g_wihhi + (n0 + nl) * II + k);
        uint32_t vl = *(const uint32_t*)(g_wihlo + (n0 + nl) * II + k);
        ((uint32_t*)(sm + XW_HI))[idx] = vh;
        ((uint32_t*)(sm + XW_LO))[idx] = vl;
    }
    __syncthreads();

    const int grp = lane >> 2, tg = lane & 3;
    float bias0[8], bias1[8];
#pragma unroll
    for (int nt = 0; nt < 8; nt++) {
        int g = n0 + nt * 8 + tg * 2;
        bias0[nt] = bih[g] + bhh[g];
        bias1[nt] = bih[g + 1] + bhh[g + 1];
    }

    const int arow = w * 16 + (lane & 15);
    const int acol = (lane >> 4) * 16;

    for (int miter = 0; miter < 8; miter++) {
        const int m0 = (blockIdx.y * 8 + miter) * 128;

        float acc[8][4];
#pragma unroll
        for (int z = 0; z < 8; z++)
#pragma unroll
            for (int r = 0; r < 4; r++) acc[z][r] = 0.f;

#pragma unroll
        for (int i = 0; i < 4; i++) {
            int s = i * 256 + tid;
            int row = s >> 3, sb = s & 7;
            int gidx = (m0 + row) * 32 + sb;
            uint4 vh = ((const uint4*)g_xhi)[gidx];
            uint4 vl = ((const uint4*)g_xlo)[gidx];
            int off = row * 128 + sb * 16;
            int sw = off ^ ((off >> 3) & 0x70);
            *(uint4*)(sm + XA_HI + sw) = vh;
            *(uint4*)(sm + XA_LO + sw) = vl;
        }
        __syncthreads();

        for (int ch = 0; ch < 4; ch++) {
            const int buf = ch & 1;
            uint4 ph[4], pl[4];
            if (ch < 3) {
#pragma unroll
                for (int i = 0; i < 4; i++) {
                    int s = i * 256 + tid;
                    int row = s >> 3, sb = s & 7;
                    int gidx = (m0 + row) * 32 + (ch + 1) * 8 + sb;
                    ph[i] = ((const uint4*)g_xhi)[gidx];
                    pl[i] = ((const uint4*)g_xlo)[gidx];
                }
            }
            const uint32_t abh = smb + XA_HI + buf * 16384;
            const uint32_t abl = smb + XA_LO + buf * 16384;
#pragma unroll
            for (int kl = 0; kl < 4; kl++) {
                const int ks = ch * 4 + kl;
                int off = arow * 128 + kl * 32 + acol;
                int sw = off ^ ((off >> 3) & 0x70);
                uint32_t ah[4], al[4];
                ldm_x4(ah, abh + sw);
                ldm_x4(al, abl + sw);
                const uint4* wh4 = (const uint4*)(sm + XW_HI) + (ks * 32 + lane) * 4;
                const uint4* wl4 = (const uint4*)(sm + XW_LO) + (ks * 32 + lane) * 4;
#pragma unroll
                for (int q4 = 0; q4 < 4; q4++) {
                    uint4 bh = wh4[q4];
                    uint4 bl = wl4[q4];
                    mma_bf16(acc[2 * q4], ah, bh.x, bh.y);
                    mma_bf16(acc[2 * q4 + 1], ah, bh.z, bh.w);
                    mma_bf16(acc[2 * q4], al, bh.x, bh.y);
                    mma_bf16(acc[2 * q4 + 1], al, bh.z, bh.w);
                    mma_bf16(acc[2 * q4], ah, bl.x, bl.y);
                    mma_bf16(acc[2 * q4 + 1], ah, bl.z, bl.w);
                }
            }
            if (ch < 3) {
                char* dh = sm + XA_HI + (buf ^ 1) * 16384;
                char* dl = sm + XA_LO + (buf ^ 1) * 16384;
#pragma unroll
                for (int i = 0; i < 4; i++) {
                    int s = i * 256 + tid;
                    int row = s >> 3, sb = s & 7;
                    int off = row * 128 + sb * 16;
                    int sw = off ^ ((off >> 3) & 0x70);
                    *(uint4*)(dh + sw) = ph[i];
                    *(uint4*)(dl + sw) = pl[i];
                }
            }
            __syncthreads();
        }

        int r0 = m0 + w * 16 + grp;
        int r1 = r0 + 8;
        size_t ob0 = ((size_t)(r0 & 255) * BB + (r0 >> 8)) * GG;
        size_t ob1 = ((size_t)(r1 & 255) * BB + (r1 >> 8)) * GG;
#pragma unroll
        for (int nt = 0; nt < 8; nt++) {
            int g = n0 + nt * 8 + tg * 2;
            float2 v0 = make_float2(acc[nt][0] + bias0[nt], acc[nt][1] + bias1[nt]);
            float2 v1 = make_float2(acc[nt][2] + bias0[nt], acc[nt][3] + bias1[nt]);
            *(float2*)&g_xproj[ob0 + g] = v0;
            *(float2*)&g_xproj[ob1 + g] = v1;
        }
    }
}

// ---------------------------------------------------------------------------
// Persistent LSTM recurrence: 128 CTAs x 256 thr.  fp16 2-term split:
//   gates = (h_hi + h_lo) @ W_fp16^T   (dropped h*W_lo term, ~1.5e-5/step)
// R5-proven structure: k128 chunks x 8, __ldcg+STS staging, per-chunk
// producer-group polls, fast-math epilogue. 4 independent MMA chains.
// ---------------------------------------------------------------------------
__global__ __launch_bounds__(256, 1) void lstm_kernel(const float* __restrict__ Whh) {
    extern __shared__ char sm[];
    const int tid = threadIdx.x;
    const int lane = tid & 31;
    const int w = tid >> 5;
    const int mt = w & 3, nh = w >> 2;
    const int hc0 = blockIdx.x * 8;
    const uint32_t smb = smem_u32(sm);

    // ---- one-time: W fragment fill (fp16, fragment-direct layout) ----
    for (int idx = tid; idx < 16384; idx += 256) {
        int r = idx & 3, ln = (idx >> 2) & 31, ks = (idx >> 7) & 63, nhh = idx >> 13;
        int nt = r >> 1;
        int kk = (r & 1) * 8 + (ln & 3) * 2;
        int nl = nhh * 16 + nt * 8 + (ln >> 2);
        int k = ks * 16 + kk;
        int gr = (nl >> 3) * 1024 + hc0 + (nl & 7);
        __half h0 = __float2half(Whh[gr * 1024 + k]);
        __half h1 = __float2half(Whh[gr * 1024 + k + 1]);
        ((uint32_t*)(sm + WF))[idx] = pack2h(h0, h1);
    }
    __syncthreads();

    // staging constants: thread handles 4 x 16B segments per half per chunk
    int ssw[4], sgix[4];
#pragma unroll
    for (int i = 0; i < 4; i++) {
        int s = i * 256 + tid;
        int row = s >> 4, seg = s & 15;
        ssw[i] = row * 256 + ((seg ^ (row & 7)) << 4);
        sgix[i] = row * 128 + seg;          // + ch*16 per chunk (uint4 units)
    }

    // A ldmatrix per-lane constants (row = arow, seg swizzled per row)
    const int arow = mt * 16 + (lane & 15);
    const int ahalf = lane >> 4;            // k-half within kstep

    // epilogue ownership: this thread handles states (b, ej) and (b, ej+4)
    const int eb = tid & 63, ej = tid >> 6;
    float c0 = 0.f, c1 = 0.f;

    for (int t = 0; t < TT; t++) {
        const uint4* ghi = (const uint4*)g_hhi[t & 1];
        const uint4* glo = (const uint4*)g_hlo[t & 1];
        const float* xg = g_xproj + (size_t)t * BB * GG;
        const unsigned tgt = 16u * (unsigned)t;

        // prefetch this thread's xproj values (4 gates x 2 states)
        float xp[8];
#pragma unroll
        for (int q = 0; q < 4; q++) {
            xp[q] = xg[(size_t)eb * GG + q * HH + hc0 + ej];
            xp[4 + q] = xg[(size_t)eb * GG + q * HH + hc0 + ej + 4];
        }

        float acc_h[2][4], acc_l[2][4];
#pragma unroll
        for (int z = 0; z < 2; z++)
#pragma unroll
            for (int r = 0; r < 4; r++) { acc_h[z][r] = 0.f; acc_l[z][r] = 0.f; }

        // prologue: wait for group 0 producers, stage chunk 0 -> buf 0
        if (t) {
            if (lane == 0) poll_ge(&g_cnt[0], tgt);
            __syncwarp();
        }
        {
            uint4 vh[4], vl[4];
#pragma unroll
            for (int i = 0; i < 4; i++) { vh[i] = __ldcg(ghi + sgix[i]); vl[i] = __ldcg(glo + sgix[i]); }
#pragma unroll
            for (int i = 0; i < 4; i++) {
                *(uint4*)(sm + A_HI + ssw[i]) = vh[i];
                *(uint4*)(sm + A_LO + ssw[i]) = vl[i];
            }
        }
        __syncthreads();

        for (int ch = 0; ch < 8; ch++) {
            const int buf = ch & 1;
            uint4 ph[4], pl[4];
            if (ch < 7) {
                if (t) {
                    if (lane == 0) poll_ge(&g_cnt[ch + 1], tgt);
                    __syncwarp();
                }
#pragma unroll
                for (int i = 0; i < 4; i++) {
                    ph[i] = __ldcg(ghi + sgix[i] + (ch + 1) * 16);
                    pl[i] = __ldcg(glo + sgix[i] + (ch + 1) * 16);
                }
            }
            const uint32_t abh = smb + A_HI + buf * 16384;
            const uint32_t abl = smb + A_LO + buf * 16384;
            const uint4* wf = (const uint4*)(sm + WF) + ((nh * 64 + ch * 8) * 32 + lane);
#pragma unroll
            for (int kl = 0; kl < 8; kl++) {
                int seg = kl * 2 + ahalf;
                int sw = arow * 256 + ((seg ^ (arow & 7)) << 4);
                uint32_t ah[4], al[4];
                ldm_x4(ah, abh + sw);
                ldm_x4(al, abl + sw);
                uint4 bh = wf[kl * 32];
                mma_f16(acc_h[0], ah, bh.x, bh.y);    // 4 independent chains
                mma_f16(acc_h[1], ah, bh.z, bh.w);
                mma_f16(acc_l[0], al, bh.x, bh.y);
                mma_f16(acc_l[1], al, bh.z, bh.w);
            }
            if (ch < 7) {
                char* dh = sm + A_HI + (buf ^ 1) * 16384;
                char* dl = sm + A_LO + (buf ^ 1) * 16384;
#pragma unroll
                for (int i = 0; i < 4; i++) {
                    *(uint4*)(dh + ssw[i]) = ph[i];
                    *(uint4*)(dl + ssw[i]) = pl[i];
                }
            }
            __syncthreads();
        }

        // epilogue: exchange D fragments via SMEM [32 cols][stride 72]
        float* sg = (float*)sm;
        {
            int grp = lane >> 2, tg = lane & 3;
#pragma unroll
            for (int nt = 0; nt < 2; nt++) {
                int col = nh * 16 + nt * 8 + tg * 2;
                int row = mt * 16 + grp;
                sg[col * 72 + row] = acc_h[nt][0] + acc_l[nt][0];
                sg[(col + 1) * 72 + row] = acc_h[nt][1] + acc_l[nt][1];
                sg[col * 72 + row + 8] = acc_h[nt][2] + acc_l[nt][2];
                sg[(col + 1) * 72 + row + 8] = acc_h[nt][3] + acc_l[nt][3];
            }
        }
        __syncthreads();

        // pointwise update (fast math): 512 states over 256 threads (2 each)
        {
            __half* hh = g_hhi[(t + 1) & 1];
            __half* hl = g_hlo[(t + 1) & 1];
            {
                float iv = sg[(0 + ej) * 72 + eb] + xp[0];
                float fv = sg[(8 + ej) * 72 + eb] + xp[1];
                float gv = sg[(16 + ej) * 72 + eb] + xp[2];
                float ov = sg[(24 + ej) * 72 + eb] + xp[3];
                float cn = fsigmoid(fv) * c0 + fsigmoid(iv) * ftanh(gv);
                c0 = cn;
                float hn = fsigmoid(ov) * ftanh(cn);
                __half hbb = __float2half(hn);
                hh[eb * HH + hc0 + ej] = hbb;
                hl[eb * HH + hc0 + ej] = __float2half(hn - __half2float(hbb));
            }
            {
                int j = ej + 4;
                float iv = sg[(0 + j) * 72 + eb] + xp[4];
                float fv = sg[(8 + j) * 72 + eb] + xp[5];
                float gv = sg[(16 + j) * 72 + eb] + xp[6];
                float ov = sg[(24 + j) * 72 + eb] + xp[7];
                float cn = fsigmoid(fv) * c1 + fsigmoid(iv) * ftanh(gv);
                c1 = cn;
                float hn = fsigmoid(ov) * ftanh(cn);
                __half hbb = __float2half(hn);
                hh[eb * HH + hc0 + j] = hbb;
                hl[eb * HH + hc0 + j] = __float2half(hn - __half2float(hbb));
            }
        }
        __syncthreads();
        if (tid == 0) {
            __threadfence();                            // order h stores (gpu scope)
            atomicAdd(&g_cnt[blockIdx.x >> 4], 1u);     // signal this group's step done
        }
    }
}

// ---------------------------------------------------------------------------
// logits = h_last @ fc_w^T + fc_b; out = log_softmax.  grid=64, block=256.
// ---------------------------------------------------------------------------
__global__ __launch_bounds__(256) void fc_kernel(const float* __restrict__ fcw,
                                                 const float* __restrict__ fcb,
                                                 float* __restrict__ out) {
    __shared__ float sh[HH];
    __shared__ float sl[64];
    __shared__ float s_red[2];
    int b = blockIdx.x;
    int tid = threadIdx.x;
    int w = tid >> 5, lane = tid & 31;

    {
        uint2 vh = ((const uint2*)(g_hhi[0] + b * HH))[tid];
        uint2 vl = ((const uint2*)(g_hlo[0] + b * HH))[tid];
        float2 h0 = unpack2h(vh.x), h1 = unpack2h(vh.y);
        float2 l0 = unpack2h(vl.x), l1 = unpack2h(vl.y);
        float4 f = make_float4(h0.x + l0.x, h0.y + l0.y, h1.x + l1.x, h1.y + l1.y);
        ((float4*)sh)[tid] = f;
    }
    __syncthreads();

#pragma unroll
    for (int cc = 0; cc < 8; cc++) {
        int c = w * 8 + cc;
        float s = 0.f;
        if (c < CC) {
            const float* wr = fcw + c * HH;
#pragma unroll 8
            for (int i = 0; i < 32; i++) {
                int k = i * 32 + lane;
                s += sh[k] * wr[k];
            }
        }
#pragma unroll
        for (int off = 16; off > 0; off >>= 1) s += __shfl_xor_sync(0xFFFFFFFF, s, off);
        if (lane == 0) sl[c] = (c < CC) ? s + fcb[c] : -1e30f;
    }
    __syncthreads();

    if (w == 0) {
        float v0 = sl[lane], v1 = sl[lane + 32];
        float m = fmaxf(v0, v1);
#pragma unroll
        for (int off = 16; off > 0; off >>= 1) m = fmaxf(m, __shfl_xor_sync(0xFFFFFFFF, m, off));
        float e = expf(v0 - m) + expf(v1 - m);
#pragma unroll
        for (int off = 16; off > 0; off >>= 1) e += __shfl_xor_sync(0xFFFFFFFF, e, off);
        if (lane == 0) { s_red[0] = m; s_red[1] = logf(e); }
    }
    __syncthreads();
    if (tid < CC) out[b * CC + tid] = sl[tid] - s_red[0] - s_red[1];
}

// ---------------------------------------------------------------------------
extern "C" void kernel_launch(void* const* d_in, const int* in_sizes, int n_in,
                              void* d_out, int out_size) {
    const float* inp = (const float*)d_in[0];   // [B,T,I]
    const float* Wih = (const float*)d_in[1];   // [4H,I]
    const float* Whh = (const float*)d_in[2];   // [4H,H]
    const float* bih = (const float*)d_in[3];   // [4H]
    const float* bhh = (const float*)d_in[4];   // [4H]
    const float* fcw = (const float*)d_in[5];   // [C,H]
    const float* fcb = (const float*)d_in[6];   // [C]
    float* out = (float*)d_out;                 // [B,C]

    cudaFuncSetAttribute(lstm_kernel, cudaFuncAttributeMaxDynamicSharedMemorySize, SMEM_DYN);
    cudaFuncSetAttribute(xproj_mma_kernel, cudaFuncAttributeMaxDynamicSharedMemorySize, SMEM_X);

    zero_kernel<<<512, 256>>>();
    conv_kernel<<<1024, 256>>>(inp, Wih);

    dim3 gx(64, 16);
    xproj_mma_kernel<<<gx, 256, SMEM_X>>>(bih, bhh);

    lstm_kernel<<<NCTA, 256, SMEM_DYN>>>(Whh);

    fc_kernel<<<BB, 64 * 4>>>(fcw, fcb, out);
}

// round 9
// speedup vs baseline: 2.0628x; 1.3686x over previous
#include <cuda_runtime.h>
#include <cuda_bf16.h>
#include <cuda_fp16.h>
#include <math.h>
#include <cstdint>

// Problem dims
constexpr int BB = 64;    // batch
constexpr int TT = 256;   // time steps
constexpr int II = 256;   // input dim
constexpr int HH = 1024;  // hidden
constexpr int CC = 60;    // classes
constexpr int GG = 4096;  // 4*H
constexpr int NCTA = 128; // persistent CTAs; each owns 8 h-cols x 4 gates = 32 gate cols

// Dynamic SMEM layout (lstm_kernel): k128 chunks, fp16 single-term
constexpr int A_B = 0;         // 2 bufs x 16KB (64 rows x 128 fp16, row=256B, seg-swizzled)
constexpr int WF = 32768;      // 64KB fragment-direct W (fp16)
constexpr int SMEM_DYN = 98304;

// Dynamic SMEM layout (xproj_mma kernel): fp16 single-term
constexpr int XA = 0;          // 2 bufs x 16KB (128 rows x 64 fp16, SW128)
constexpr int XW = 32768;      // 32KB fragment-direct W_ih (fp16, 64 cols x 256 k)
constexpr int SMEM_X = 65536;

// Scratch (__device__ globals: allocation-free)
__device__ float g_xproj[(size_t)TT * BB * GG];   // [t][b][g]
__device__ __half g_hhi[2][BB * HH];              // h (fp16), ping-pong
__device__ __half g_hlo[2][BB * HH];              // h lo correction (final step only)
__device__ __half g_xh[BB * TT * II];             // inputs fp16  [(b*T+t)][i]
__device__ __half g_wih[GG * II];                 // W_ih fp16 [g][i]
__device__ unsigned g_cnt[8];                     // per-column-group step counters

// ---------------------------------------------------------------------------
// helpers
// ---------------------------------------------------------------------------
__device__ __forceinline__ uint32_t smem_u32(const void* p) {
    uint32_t a;
    asm("{ .reg .u64 t; cvta.to.shared.u64 t, %1; cvt.u32.u64 %0, t; }" : "=r"(a) : "l"(p));
    return a;
}
__device__ __forceinline__ void ldm_x4(uint32_t* r, uint32_t addr) {
    asm volatile("ldmatrix.sync.aligned.m8n8.x4.shared.b16 {%0,%1,%2,%3}, [%4];"
                 : "=r"(r[0]), "=r"(r[1]), "=r"(r[2]), "=r"(r[3]) : "r"(addr));
}
__device__ __forceinline__ void mma_f16(float* d, const uint32_t* a, uint32_t b0, uint32_t b1) {
    asm volatile(
        "mma.sync.aligned.m16n8k16.row.col.f32.f16.f16.f32 "
        "{%0,%1,%2,%3}, {%4,%5,%6,%7}, {%8,%9}, {%0,%1,%2,%3};"
        : "+f"(d[0]), "+f"(d[1]), "+f"(d[2]), "+f"(d[3])
        : "r"(a[0]), "r"(a[1]), "r"(a[2]), "r"(a[3]), "r"(b0), "r"(b1));
}
__device__ __forceinline__ uint32_t pack2h(__half a, __half b) {
    return (uint32_t)*(uint16_t*)&a | ((uint32_t)*(uint16_t*)&b << 16);
}
__device__ __forceinline__ float2 unpack2h(uint32_t v) {
    __half2 h = *(__half2*)&v;
    return __half22float2(h);
}
__device__ __forceinline__ void poll_ge(const unsigned* p, unsigned tgt) {
    unsigned v;
    do {
        asm volatile("ld.acquire.gpu.global.u32 %0, [%1];" : "=r"(v) : "l"(p) : "memory");
    } while (v < tgt);
}
__device__ __forceinline__ float fsigmoid(float x) {
    return __fdividef(1.f, 1.f + __expf(-x));
}
__device__ __forceinline__ float ftanh(float x) {
    return 1.f - __fdividef(2.f, __expf(2.f * x) + 1.f);
}

// ---------------------------------------------------------------------------
// Zero-init h buffers + group counters.
// ---------------------------------------------------------------------------
__global__ void zero_kernel() {
    int i = blockIdx.x * blockDim.x + threadIdx.x;
    if (i < BB * HH) {            // u32 words cover both ping-pong buffers
        ((unsigned*)g_hhi)[i] = 0u;
        ((unsigned*)g_hlo)[i] = 0u;
    }
    if (i < 8) g_cnt[i] = 0u;
}

// ---------------------------------------------------------------------------
// Convert inputs and W_ih to fp16 (row-major, same layout).
// ---------------------------------------------------------------------------
__global__ void conv_kernel(const float* __restrict__ inp, const float* __restrict__ Wih) {
    int stride = gridDim.x * blockDim.x;
    int i0 = blockIdx.x * blockDim.x + threadIdx.x;
    for (int i = i0; i < 1048576; i += stride) {       // inputs: 1M float4
        float4 v = ((const float4*)inp)[i];
        uint2 h = make_uint2(pack2h(__float2half(v.x), __float2half(v.y)),
                             pack2h(__float2half(v.z), __float2half(v.w)));
        ((uint2*)g_xh)[i] = h;
    }
    for (int i = i0; i < 262144; i += stride) {        // W_ih: 256K float4
        float4 v = ((const float4*)Wih)[i];
        uint2 h = make_uint2(pack2h(__float2half(v.x), __float2half(v.y)),
                             pack2h(__float2half(v.z), __float2half(v.w)));
        ((uint2*)g_wih)[i] = h;
    }
}

// ---------------------------------------------------------------------------
// x_proj via fp16 single-term mma.sync.  M=16384 rows (r=b*256+t), N=4096,
// K=256. grid (64, 16); W tile resident fragment-direct; 8 M-tiles per CTA.
// ---------------------------------------------------------------------------
__global__ __launch_bounds__(256, 1) void xproj_mma_kernel(
    const float* __restrict__ bih, const float* __restrict__ bhh) {
    extern __shared__ char sm[];
    const int tid = threadIdx.x;
    const int lane = tid & 31;
    const int w = tid >> 5;
    const int n0 = blockIdx.x * 64;
    const uint32_t smb = smem_u32(sm);

    // W fragment fill (8192 u32, fp16)
    for (int idx = tid; idx < 8192; idx += 256) {
        int q = idx & 15, ln = (idx >> 4) & 31, ks = idx >> 9;
        int nt = q >> 1, rr = q & 1;
        int nl = nt * 8 + (ln >> 2);
        int k = ks * 16 + rr * 8 + (ln & 3) * 2;
        ((uint32_t*)(sm + XW))[idx] = *(const uint32_t*)(g_wih + (n0 + nl) * II + k);
    }
    __syncthreads();

    const int grp = lane >> 2, tg = lane & 3;
    float bias0[8], bias1[8];
#pragma unroll
    for (int nt = 0; nt < 8; nt++) {
        int g = n0 + nt * 8 + tg * 2;
        bias0[nt] = bih[g] + bhh[g];
        bias1[nt] = bih[g + 1] + bhh[g + 1];
    }

    const int arow = w * 16 + (lane & 15);
    const int acol = (lane >> 4) * 16;

    for (int miter = 0; miter < 8; miter++) {
        const int m0 = (blockIdx.y * 8 + miter) * 128;

        float acc[8][4];
#pragma unroll
        for (int z = 0; z < 8; z++)
#pragma unroll
            for (int r = 0; r < 4; r++) acc[z][r] = 0.f;

        // prologue: chunk 0 -> buf 0 (4 x 16B segments per thread)
#pragma unroll
        for (int i = 0; i < 4; i++) {
            int s = i * 256 + tid;
            int row = s >> 3, sb = s & 7;
            uint4 v = ((const uint4*)g_xh)[(m0 + row) * 32 + sb];
            int off = row * 128 + sb * 16;
            int sw = off ^ ((off >> 3) & 0x70);
            *(uint4*)(sm + XA + sw) = v;
        }
        __syncthreads();

        for (int ch = 0; ch < 4; ch++) {
            const int buf = ch & 1;
            uint4 ph[4];
            if (ch < 3) {
#pragma unroll
                for (int i = 0; i < 4; i++) {
                    int s = i * 256 + tid;
                    int row = s >> 3, sb = s & 7;
                    ph[i] = ((const uint4*)g_xh)[(m0 + row) * 32 + (ch + 1) * 8 + sb];
                }
            }
            const uint32_t ab = smb + XA + buf * 16384;
#pragma unroll
            for (int kl = 0; kl < 4; kl++) {
                const int ks = ch * 4 + kl;
                int off = arow * 128 + kl * 32 + acol;
                int sw = off ^ ((off >> 3) & 0x70);
                uint32_t ah[4];
                ldm_x4(ah, ab + sw);
                const uint4* wh4 = (const uint4*)(sm + XW) + (ks * 32 + lane) * 4;
#pragma unroll
                for (int q4 = 0; q4 < 4; q4++) {
                    uint4 bh = wh4[q4];
                    mma_f16(acc[2 * q4], ah, bh.x, bh.y);
                    mma_f16(acc[2 * q4 + 1], ah, bh.z, bh.w);
                }
            }
            if (ch < 3) {
                char* dh = sm + XA + (buf ^ 1) * 16384;
#pragma unroll
                for (int i = 0; i < 4; i++) {
                    int s = i * 256 + tid;
                    int row = s >> 3, sb = s & 7;
                    int off = row * 128 + sb * 16;
                    int sw = off ^ ((off >> 3) & 0x70);
                    *(uint4*)(dh + sw) = ph[i];
                }
            }
            __syncthreads();
        }

        int r0 = m0 + w * 16 + grp;
        int r1 = r0 + 8;
        size_t ob0 = ((size_t)(r0 & 255) * BB + (r0 >> 8)) * GG;
        size_t ob1 = ((size_t)(r1 & 255) * BB + (r1 >> 8)) * GG;
#pragma unroll
        for (int nt = 0; nt < 8; nt++) {
            int g = n0 + nt * 8 + tg * 2;
            float2 v0 = make_float2(acc[nt][0] + bias0[nt], acc[nt][1] + bias1[nt]);
            float2 v1 = make_float2(acc[nt][2] + bias0[nt], acc[nt][3] + bias1[nt]);
            *(float2*)&g_xproj[ob0 + g] = v0;
            *(float2*)&g_xproj[ob1 + g] = v1;
        }
    }
}

// ---------------------------------------------------------------------------
// Persistent LSTM recurrence: 128 CTAs x 256 thr.  fp16 single-term:
//   gates = h_fp16 @ W_fp16^T      (validated error-damping budget)
// R5/R8-proven skeleton: k128 chunks x 8, __ldcg+STS staging, per-chunk
// producer-group polls, fast-math epilogue. 4 chains via even/odd k-steps.
// ---------------------------------------------------------------------------
__global__ __launch_bounds__(256, 1) void lstm_kernel(const float* __restrict__ Whh) {
    extern __shared__ char sm[];
    const int tid = threadIdx.x;
    const int lane = tid & 31;
    const int w = tid >> 5;
    const int mt = w & 3, nh = w >> 2;
    const int hc0 = blockIdx.x * 8;
    const uint32_t smb = smem_u32(sm);

    // ---- one-time: W fragment fill (fp16, fragment-direct layout) ----
    for (int idx = tid; idx < 16384; idx += 256) {
        int r = idx & 3, ln = (idx >> 2) & 31, ks = (idx >> 7) & 63, nhh = idx >> 13;
        int nt = r >> 1;
        int kk = (r & 1) * 8 + (ln & 3) * 2;
        int nl = nhh * 16 + nt * 8 + (ln >> 2);
        int k = ks * 16 + kk;
        int gr = (nl >> 3) * 1024 + hc0 + (nl & 7);
        __half h0 = __float2half(Whh[gr * 1024 + k]);
        __half h1 = __float2half(Whh[gr * 1024 + k + 1]);
        ((uint32_t*)(sm + WF))[idx] = pack2h(h0, h1);
    }
    __syncthreads();

    // staging constants: thread handles 4 x 16B segments per chunk
    int ssw[4], sgix[4];
#pragma unroll
    for (int i = 0; i < 4; i++) {
        int s = i * 256 + tid;
        int row = s >> 4, seg = s & 15;
        ssw[i] = row * 256 + ((seg ^ (row & 7)) << 4);
        sgix[i] = row * 128 + seg;          // + ch*16 per chunk (uint4 units)
    }

    // A ldmatrix per-lane constants
    const int arow = mt * 16 + (lane & 15);
    const int ahalf = lane >> 4;            // k-half within kstep

    // epilogue ownership: this thread handles states (b, ej) and (b, ej+4)
    const int eb = tid & 63, ej = tid >> 6;
    float c0 = 0.f, c1 = 0.f;

    for (int t = 0; t < TT; t++) {
        const uint4* gh = (const uint4*)g_hhi[t & 1];
        const float* xg = g_xproj + (size_t)t * BB * GG;
        const unsigned tgt = 16u * (unsigned)t;

        // prefetch this thread's xproj values (4 gates x 2 states)
        float xp[8];
#pragma unroll
        for (int q = 0; q < 4; q++) {
            xp[q] = xg[(size_t)eb * GG + q * HH + hc0 + ej];
            xp[4 + q] = xg[(size_t)eb * GG + q * HH + hc0 + ej + 4];
        }

        float acc[4][4];    // [ (kl&1)*2 + nt ][4] : 4 independent chains
#pragma unroll
        for (int z = 0; z < 4; z++)
#pragma unroll
            for (int r = 0; r < 4; r++) acc[z][r] = 0.f;

        // prologue: wait for group 0 producers, stage chunk 0 -> buf 0
        if (t) {
            if (lane == 0) poll_ge(&g_cnt[0], tgt);
            __syncwarp();
        }
        {
            uint4 vh[4];
#pragma unroll
            for (int i = 0; i < 4; i++) vh[i] = __ldcg(gh + sgix[i]);
#pragma unroll
            for (int i = 0; i < 4; i++) *(uint4*)(sm + A_B + ssw[i]) = vh[i];
        }
        __syncthreads();

        for (int ch = 0; ch < 8; ch++) {
            const int buf = ch & 1;
            uint4 ph[4];
            if (ch < 7) {
                if (t) {
                    if (lane == 0) poll_ge(&g_cnt[ch + 1], tgt);
                    __syncwarp();
                }
#pragma unroll
                for (int i = 0; i < 4; i++) ph[i] = __ldcg(gh + sgix[i] + (ch + 1) * 16);
            }
            const uint32_t ab = smb + A_B + buf * 16384;
            const uint4* wf = (const uint4*)(sm + WF) + ((nh * 64 + ch * 8) * 32 + lane);
#pragma unroll
            for (int kl = 0; kl < 8; kl++) {
                int seg = kl * 2 + ahalf;
                int sw = arow * 256 + ((seg ^ (arow & 7)) << 4);
                uint32_t ah[4];
                ldm_x4(ah, ab + sw);
                uint4 bh = wf[kl * 32];
                int z = (kl & 1) * 2;
                mma_f16(acc[z], ah, bh.x, bh.y);
                mma_f16(acc[z + 1], ah, bh.z, bh.w);
            }
            if (ch < 7) {
                char* dh = sm + A_B + (buf ^ 1) * 16384;
#pragma unroll
                for (int i = 0; i < 4; i++) *(uint4*)(dh + ssw[i]) = ph[i];
            }
            __syncthreads();
        }

        // epilogue: exchange D fragments via SMEM [32 cols][stride 72]
        float* sg = (float*)sm;
        {
            int grp = lane >> 2, tg = lane & 3;
#pragma unroll
            for (int nt = 0; nt < 2; nt++) {
                int col = nh * 16 + nt * 8 + tg * 2;
                int row = mt * 16 + grp;
                sg[col * 72 + row] = acc[nt][0] + acc[2 + nt][0];
                sg[(col + 1) * 72 + row] = acc[nt][1] + acc[2 + nt][1];
                sg[col * 72 + row + 8] = acc[nt][2] + acc[2 + nt][2];
                sg[(col + 1) * 72 + row + 8] = acc[nt][3] + acc[2 + nt][3];
            }
        }
        __syncthreads();

        // pointwise update (fast math): 512 states over 256 threads (2 each)
        {
            __half* hh = g_hhi[(t + 1) & 1];
            __half* hl = g_hlo[(t + 1) & 1];
            const bool last = (t == TT - 1);
            {
                float iv = sg[(0 + ej) * 72 + eb] + xp[0];
                float fv = sg[(8 + ej) * 72 + eb] + xp[1];
                float gv = sg[(16 + ej) * 72 + eb] + xp[2];
                float ov = sg[(24 + ej) * 72 + eb] + xp[3];
                float cn = fsigmoid(fv) * c0 + fsigmoid(iv) * ftanh(gv);
                c0 = cn;
                float hn = fsigmoid(ov) * ftanh(cn);
                __half hbb = __float2half(hn);
                hh[eb * HH + hc0 + ej] = hbb;
                if (last) hl[eb * HH + hc0 + ej] = __float2half(hn - __half2float(hbb));
            }
            {
                int j = ej + 4;
                float iv = sg[(0 + j) * 72 + eb] + xp[4];
                float fv = sg[(8 + j) * 72 + eb] + xp[5];
                float gv = sg[(16 + j) * 72 + eb] + xp[6];
                float ov = sg[(24 + j) * 72 + eb] + xp[7];
                float cn = fsigmoid(fv) * c1 + fsigmoid(iv) * ftanh(gv);
                c1 = cn;
                float hn = fsigmoid(ov) * ftanh(cn);
                __half hbb = __float2half(hn);
                hh[eb * HH + hc0 + j] = hbb;
                if (last) hl[eb * HH + hc0 + j] = __float2half(hn - __half2float(hbb));
            }
        }
        __syncthreads();
        if (tid == 0) {
            __threadfence();                            // order h stores (gpu scope)
            atomicAdd(&g_cnt[blockIdx.x >> 4], 1u);     // signal this group's step done
        }
    }
}

// ---------------------------------------------------------------------------
// logits = h_last @ fc_w^T + fc_b; out = log_softmax.  grid=64, block=256.
// h_last = g_hhi[0] + g_hlo[0]  (full precision at the final step)
// ---------------------------------------------------------------------------
__global__ __launch_bounds__(256) void fc_kernel(const float* __restrict__ fcw,
                                                 const float* __restrict__ fcb,
                                                 float* __restrict__ out) {
    __shared__ float sh[HH];
    __shared__ float sl[64];
    __shared__ float s_red[2];
    int b = blockIdx.x;
    int tid = threadIdx.x;
    int w = tid >> 5, lane = tid & 31;

    {
        uint2 vh = ((const uint2*)(g_hhi[0] + b * HH))[tid];
        uint2 vl = ((const uint2*)(g_hlo[0] + b * HH))[tid];
        float2 h0 = unpack2h(vh.x), h1 = unpack2h(vh.y);
        float2 l0 = unpack2h(vl.x), l1 = unpack2h(vl.y);
        float4 f = make_float4(h0.x + l0.x, h0.y + l0.y, h1.x + l1.x, h1.y + l1.y);
        ((float4*)sh)[tid] = f;
    }
    __syncthreads();

#pragma unroll
    for (int cc = 0; cc < 8; cc++) {
        int c = w * 8 + cc;
        float s = 0.f;
        if (c < CC) {
            const float* wr = fcw + c * HH;
#pragma unroll 8
            for (int i = 0; i < 32; i++) {
                int k = i * 32 + lane;
                s += sh[k] * wr[k];
            }
        }
#pragma unroll
        for (int off = 16; off > 0; off >>= 1) s += __shfl_xor_sync(0xFFFFFFFF, s, off);
        if (lane == 0) sl[c] = (c < CC) ? s + fcb[c] : -1e30f;
    }
    __syncthreads();

    if (w == 0) {
        float v0 = sl[lane], v1 = sl[lane + 32];
        float m = fmaxf(v0, v1);
#pragma unroll
        for (int off = 16; off > 0; off >>= 1) m = fmaxf(m, __shfl_xor_sync(0xFFFFFFFF, m, off));
        float e = expf(v0 - m) + expf(v1 - m);
#pragma unroll
        for (int off = 16; off > 0; off >>= 1) e += __shfl_xor_sync(0xFFFFFFFF, e, off);
        if (lane == 0) { s_red[0] = m; s_red[1] = logf(e); }
    }
    __syncthreads();
    if (tid < CC) out[b * CC + tid] = sl[tid] - s_red[0] - s_red[1];
}

// ---------------------------------------------------------------------------
extern "C" void kernel_launch(void* const* d_in, const int* in_sizes, int n_in,
                              void* d_out, int out_size) {
    const float* inp = (const float*)d_in[0];   // [B,T,I]
    const float* Wih = (const float*)d_in[1];   // [4H,I]
    const float* Whh = (const float*)d_in[2];   // [4H,H]
    const float* bih = (const float*)d_in[3];   // [4H]
    const float* bhh = (const float*)d_in[4];   // [4H]
    const float* fcw = (const float*)d_in[5];   // [C,H]
    const float* fcb = (const float*)d_in[6];   // [C]
    float* out = (float*)d_out;                 // [B,C]

    cudaFuncSetAttribute(lstm_kernel, cudaFuncAttributeMaxDynamicSharedMemorySize, SMEM_DYN);
    cudaFuncSetAttribute(xproj_mma_kernel, cudaFuncAttributeMaxDynamicSharedMemorySize, SMEM_X);

    zero_kernel<<<512, 256>>>();
    conv_kernel<<<1024, 256>>>(inp, Wih);

    dim3 gx(64, 16);
    xproj_mma_kernel<<<gx, 256, SMEM_X>>>(bih, bhh);

    lstm_kernel<<<NCTA, 256, SMEM_DYN>>>(Whh);

    fc_kernel<<<BB, 64 * 4>>>(fcw, fcb, out);
}

// round 10
// speedup vs baseline: 2.0799x; 1.0083x over previous
#include <cuda_runtime.h>
#include <cuda_bf16.h>
#include <cuda_fp16.h>
#include <math.h>
#include <cstdint>

// Problem dims
constexpr int BB = 64;    // batch
constexpr int TT = 256;   // time steps
constexpr int II = 256;   // input dim
constexpr int HH = 1024;  // hidden
constexpr int CC = 60;    // classes
constexpr int GG = 4096;  // 4*H
constexpr int NCTA = 128; // persistent CTAs; each owns 8 h-cols x 4 gates = 32 gate cols

// Dynamic SMEM layout (lstm_kernel): k128 chunks, fp16 single-term
constexpr int A_B = 0;         // 2 bufs x 16KB (64 rows x 128 fp16, row=256B, seg-swizzled)
constexpr int WF = 32768;      // 64KB fragment-direct W (fp16)
constexpr int SMEM_DYN = 98304;

// Dynamic SMEM layout (xproj_mma kernel): fp16 single-term
constexpr int XA = 0;          // 2 bufs x 16KB (128 rows x 64 fp16, SW128)
constexpr int XW = 32768;      // 32KB fragment-direct W_ih (fp16, 64 cols x 256 k)
constexpr int SMEM_X = 65536;

// Scratch (__device__ globals: allocation-free)
__device__ float g_xproj[(size_t)TT * BB * GG];   // [t][b][g]
__device__ __half g_hhi[2][BB * HH];              // h (fp16), ping-pong
__device__ __half g_hlo[2][BB * HH];              // h lo correction (final step only)
__device__ __half g_xh[BB * TT * II];             // inputs fp16  [(b*T+t)][i]
__device__ __half g_wih[GG * II];                 // W_ih fp16 [g][i]
__device__ unsigned g_cnt[8];                     // per-column-group step counters

// ---------------------------------------------------------------------------
// helpers
// ---------------------------------------------------------------------------
__device__ __forceinline__ uint32_t smem_u32(const void* p) {
    uint32_t a;
    asm("{ .reg .u64 t; cvta.to.shared.u64 t, %1; cvt.u32.u64 %0, t; }" : "=r"(a) : "l"(p));
    return a;
}
__device__ __forceinline__ void ldm_x4(uint32_t* r, uint32_t addr) {
    asm volatile("ldmatrix.sync.aligned.m8n8.x4.shared.b16 {%0,%1,%2,%3}, [%4];"
                 : "=r"(r[0]), "=r"(r[1]), "=r"(r[2]), "=r"(r[3]) : "r"(addr));
}
__device__ __forceinline__ void mma_f16(float* d, const uint32_t* a, uint32_t b0, uint32_t b1) {
    asm volatile(
        "mma.sync.aligned.m16n8k16.row.col.f32.f16.f16.f32 "
        "{%0,%1,%2,%3}, {%4,%5,%6,%7}, {%8,%9}, {%0,%1,%2,%3};"
        : "+f"(d[0]), "+f"(d[1]), "+f"(d[2]), "+f"(d[3])
        : "r"(a[0]), "r"(a[1]), "r"(a[2]), "r"(a[3]), "r"(b0), "r"(b1));
}
__device__ __forceinline__ uint32_t pack2h(__half a, __half b) {
    return (uint32_t)*(uint16_t*)&a | ((uint32_t)*(uint16_t*)&b << 16);
}
__device__ __forceinline__ float2 unpack2h(uint32_t v) {
    __half2 h = *(__half2*)&v;
    return __half22float2(h);
}
__device__ __forceinline__ void poll_ge(const unsigned* p, unsigned tgt) {
    unsigned v;
    do {
        asm volatile("ld.acquire.gpu.global.u32 %0, [%1];" : "=r"(v) : "l"(p) : "memory");
    } while (v < tgt);
}
// HW tanh: single MUFU op (sm_75+); sigmoid via tanh identity (1 MUFU + 1 FFMA)
__device__ __forceinline__ float ftanh(float x) {
    float y;
    asm("tanh.approx.f32 %0, %1;" : "=f"(y) : "f"(x));
    return y;
}
__device__ __forceinline__ float fsigmoid(float x) {
    return fmaf(ftanh(0.5f * x), 0.5f, 0.5f);
}

// ---------------------------------------------------------------------------
// Zero-init h buffers + group counters.
// ---------------------------------------------------------------------------
__global__ void zero_kernel() {
    int i = blockIdx.x * blockDim.x + threadIdx.x;
    if (i < BB * HH) {            // u32 words cover both ping-pong buffers
        ((unsigned*)g_hhi)[i] = 0u;
        ((unsigned*)g_hlo)[i] = 0u;
    }
    if (i < 8) g_cnt[i] = 0u;
}

// ---------------------------------------------------------------------------
// Convert inputs and W_ih to fp16 (row-major, same layout).
// ---------------------------------------------------------------------------
__global__ void conv_kernel(const float* __restrict__ inp, const float* __restrict__ Wih) {
    int stride = gridDim.x * blockDim.x;
    int i0 = blockIdx.x * blockDim.x + threadIdx.x;
    for (int i = i0; i < 1048576; i += stride) {       // inputs: 1M float4
        float4 v = ((const float4*)inp)[i];
        uint2 h = make_uint2(pack2h(__float2half(v.x), __float2half(v.y)),
                             pack2h(__float2half(v.z), __float2half(v.w)));
        ((uint2*)g_xh)[i] = h;
    }
    for (int i = i0; i < 262144; i += stride) {        // W_ih: 256K float4
        float4 v = ((const float4*)Wih)[i];
        uint2 h = make_uint2(pack2h(__float2half(v.x), __float2half(v.y)),
                             pack2h(__float2half(v.z), __float2half(v.w)));
        ((uint2*)g_wih)[i] = h;
    }
}

// ---------------------------------------------------------------------------
// x_proj via fp16 single-term mma.sync.  M=16384 rows (r=b*256+t), N=4096,
// K=256. grid (64, 16); W tile resident fragment-direct; 8 M-tiles per CTA.
// ---------------------------------------------------------------------------
__global__ __launch_bounds__(256, 1) void xproj_mma_kernel(
    const float* __restrict__ bih, const float* __restrict__ bhh) {
    extern __shared__ char sm[];
    const int tid = threadIdx.x;
    const int lane = tid & 31;
    const int w = tid >> 5;
    const int n0 = blockIdx.x * 64;
    const uint32_t smb = smem_u32(sm);

    // W fragment fill (8192 u32, fp16)
    for (int idx = tid; idx < 8192; idx += 256) {
        int q = idx & 15, ln = (idx >> 4) & 31, ks = idx >> 9;
        int nt = q >> 1, rr = q & 1;
        int nl = nt * 8 + (ln >> 2);
        int k = ks * 16 + rr * 8 + (ln & 3) * 2;
        ((uint32_t*)(sm + XW))[idx] = *(const uint32_t*)(g_wih + (n0 + nl) * II + k);
    }
    __syncthreads();

    const int grp = lane >> 2, tg = lane & 3;
    float bias0[8], bias1[8];
#pragma unroll
    for (int nt = 0; nt < 8; nt++) {
        int g = n0 + nt * 8 + tg * 2;
        bias0[nt] = bih[g] + bhh[g];
        bias1[nt] = bih[g + 1] + bhh[g + 1];
    }

    const int arow = w * 16 + (lane & 15);
    const int acol = (lane >> 4) * 16;

    for (int miter = 0; miter < 8; miter++) {
        const int m0 = (blockIdx.y * 8 + miter) * 128;

        float acc[8][4];
#pragma unroll
        for (int z = 0; z < 8; z++)
#pragma unroll
            for (int r = 0; r < 4; r++) acc[z][r] = 0.f;

        // prologue: chunk 0 -> buf 0 (4 x 16B segments per thread)
#pragma unroll
        for (int i = 0; i < 4; i++) {
            int s = i * 256 + tid;
            int row = s >> 3, sb = s & 7;
            uint4 v = ((const uint4*)g_xh)[(m0 + row) * 32 + sb];
            int off = row * 128 + sb * 16;
            int sw = off ^ ((off >> 3) & 0x70);
            *(uint4*)(sm + XA + sw) = v;
        }
        __syncthreads();

        for (int ch = 0; ch < 4; ch++) {
            const int buf = ch & 1;
            uint4 ph[4];
            if (ch < 3) {
#pragma unroll
                for (int i = 0; i < 4; i++) {
                    int s = i * 256 + tid;
                    int row = s >> 3, sb = s & 7;
                    ph[i] = ((const uint4*)g_xh)[(m0 + row) * 32 + (ch + 1) * 8 + sb];
                }
            }
            const uint32_t ab = smb + XA + buf * 16384;
#pragma unroll
            for (int kl = 0; kl < 4; kl++) {
                const int ks = ch * 4 + kl;
                int off = arow * 128 + kl * 32 + acol;
                int sw = off ^ ((off >> 3) & 0x70);
                uint32_t ah[4];
                ldm_x4(ah, ab + sw);
                const uint4* wh4 = (const uint4*)(sm + XW) + (ks * 32 + lane) * 4;
#pragma unroll
                for (int q4 = 0; q4 < 4; q4++) {
                    uint4 bh = wh4[q4];
                    mma_f16(acc[2 * q4], ah, bh.x, bh.y);
                    mma_f16(acc[2 * q4 + 1], ah, bh.z, bh.w);
                }
            }
            if (ch < 3) {
                char* dh = sm + XA + (buf ^ 1) * 16384;
#pragma unroll
                for (int i = 0; i < 4; i++) {
                    int s = i * 256 + tid;
                    int row = s >> 3, sb = s & 7;
                    int off = row * 128 + sb * 16;
                    int sw = off ^ ((off >> 3) & 0x70);
                    *(uint4*)(dh + sw) = ph[i];
                }
            }
            __syncthreads();
        }

        int r0 = m0 + w * 16 + grp;
        int r1 = r0 + 8;
        size_t ob0 = ((size_t)(r0 & 255) * BB + (r0 >> 8)) * GG;
        size_t ob1 = ((size_t)(r1 & 255) * BB + (r1 >> 8)) * GG;
#pragma unroll
        for (int nt = 0; nt < 8; nt++) {
            int g = n0 + nt * 8 + tg * 2;
            float2 v0 = make_float2(acc[nt][0] + bias0[nt], acc[nt][1] + bias1[nt]);
            float2 v1 = make_float2(acc[nt][2] + bias0[nt], acc[nt][3] + bias1[nt]);
            *(float2*)&g_xproj[ob0 + g] = v0;
            *(float2*)&g_xproj[ob1 + g] = v1;
        }
    }
}

// ---------------------------------------------------------------------------
// Persistent LSTM recurrence: 128 CTAs x 256 thr.  fp16 single-term:
//   gates = h_fp16 @ W_fp16^T      (validated error-damping budget)
// R5/R8-proven skeleton: k128 chunks x 8, __ldcg+STS staging, per-chunk
// producer-group polls, HW-tanh epilogue. 4 chains via even/odd k-steps.
// ---------------------------------------------------------------------------
__global__ __launch_bounds__(256, 1) void lstm_kernel(const float* __restrict__ Whh) {
    extern __shared__ char sm[];
    const int tid = threadIdx.x;
    const int lane = tid & 31;
    const int w = tid >> 5;
    const int mt = w & 3, nh = w >> 2;
    const int hc0 = blockIdx.x * 8;
    const uint32_t smb = smem_u32(sm);

    // ---- one-time: W fragment fill (fp16, fragment-direct layout) ----
    for (int idx = tid; idx < 16384; idx += 256) {
        int r = idx & 3, ln = (idx >> 2) & 31, ks = (idx >> 7) & 63, nhh = idx >> 13;
        int nt = r >> 1;
        int kk = (r & 1) * 8 + (ln & 3) * 2;
        int nl = nhh * 16 + nt * 8 + (ln >> 2);
        int k = ks * 16 + kk;
        int gr = (nl >> 3) * 1024 + hc0 + (nl & 7);
        __half h0 = __float2half(Whh[gr * 1024 + k]);
        __half h1 = __float2half(Whh[gr * 1024 + k + 1]);
        ((uint32_t*)(sm + WF))[idx] = pack2h(h0, h1);
    }
    __syncthreads();

    // staging constants: thread handles 4 x 16B segments per chunk
    int ssw[4], sgix[4];
#pragma unroll
    for (int i = 0; i < 4; i++) {
        int s = i * 256 + tid;
        int row = s >> 4, seg = s & 15;
        ssw[i] = row * 256 + ((seg ^ (row & 7)) << 4);
        sgix[i] = row * 128 + seg;          // + ch*16 per chunk (uint4 units)
    }

    // A ldmatrix per-lane constants
    const int arow = mt * 16 + (lane & 15);
    const int ahalf = lane >> 4;            // k-half within kstep

    // epilogue ownership: this thread handles states (b, ej) and (b, ej+4)
    const int eb = tid & 63, ej = tid >> 6;
    float c0 = 0.f, c1 = 0.f;

    for (int t = 0; t < TT; t++) {
        const uint4* gh = (const uint4*)g_hhi[t & 1];
        const float* xg = g_xproj + (size_t)t * BB * GG;
        const unsigned tgt = 16u * (unsigned)t;

        // prefetch this thread's xproj values (4 gates x 2 states)
        float xp[8];
#pragma unroll
        for (int q = 0; q < 4; q++) {
            xp[q] = xg[(size_t)eb * GG + q * HH + hc0 + ej];
            xp[4 + q] = xg[(size_t)eb * GG + q * HH + hc0 + ej + 4];
        }

        float acc[4][4];    // [ (kl&1)*2 + nt ][4] : 4 independent chains
#pragma unroll
        for (int z = 0; z < 4; z++)
#pragma unroll
            for (int r = 0; r < 4; r++) acc[z][r] = 0.f;

        // prologue: wait for group 0 producers, stage chunk 0 -> buf 0
        if (t) {
            if (lane == 0) poll_ge(&g_cnt[0], tgt);
            __syncwarp();
        }
        {
            uint4 vh[4];
#pragma unroll
            for (int i = 0; i < 4; i++) vh[i] = __ldcg(gh + sgix[i]);
#pragma unroll
            for (int i = 0; i < 4; i++) *(uint4*)(sm + A_B + ssw[i]) = vh[i];
        }
        __syncthreads();

        for (int ch = 0; ch < 8; ch++) {
            const int buf = ch & 1;
            uint4 ph[4];
            if (ch < 7) {
                if (t) {
                    if (lane == 0) poll_ge(&g_cnt[ch + 1], tgt);
                    __syncwarp();
                }
#pragma unroll
                for (int i = 0; i < 4; i++) ph[i] = __ldcg(gh + sgix[i] + (ch + 1) * 16);
            }
            const uint32_t ab = smb + A_B + buf * 16384;
            const uint4* wf = (const uint4*)(sm + WF) + ((nh * 64 + ch * 8) * 32 + lane);
#pragma unroll
            for (int kl = 0; kl < 8; kl++) {
                int seg = kl * 2 + ahalf;
                int sw = arow * 256 + ((seg ^ (arow & 7)) << 4);
                uint32_t ah[4];
                ldm_x4(ah, ab + sw);
                uint4 bh = wf[kl * 32];
                int z = (kl & 1) * 2;
                mma_f16(acc[z], ah, bh.x, bh.y);
                mma_f16(acc[z + 1], ah, bh.z, bh.w);
            }
            if (ch < 7) {
                char* dh = sm + A_B + (buf ^ 1) * 16384;
#pragma unroll
                for (int i = 0; i < 4; i++) *(uint4*)(dh + ssw[i]) = ph[i];
            }
            __syncthreads();
        }

        // epilogue: exchange D fragments via SMEM [32 cols][stride 72]
        float* sg = (float*)sm;
        {
            int grp = lane >> 2, tg = lane & 3;
#pragma unroll
            for (int nt = 0; nt < 2; nt++) {
                int col = nh * 16 + nt * 8 + tg * 2;
                int row = mt * 16 + grp;
                sg[col * 72 + row] = acc[nt][0] + acc[2 + nt][0];
                sg[(col + 1) * 72 + row] = acc[nt][1] + acc[2 + nt][1];
                sg[col * 72 + row + 8] = acc[nt][2] + acc[2 + nt][2];
                sg[(col + 1) * 72 + row + 8] = acc[nt][3] + acc[2 + nt][3];
            }
        }
        __syncthreads();

        // pointwise update (HW tanh): 512 states over 256 threads (2 each)
        {
            __half* hh = g_hhi[(t + 1) & 1];
            __half* hl = g_hlo[(t + 1) & 1];
            const bool last = (t == TT - 1);
            {
                float iv = sg[(0 + ej) * 72 + eb] + xp[0];
                float fv = sg[(8 + ej) * 72 + eb] + xp[1];
                float gv = sg[(16 + ej) * 72 + eb] + xp[2];
                float ov = sg[(24 + ej) * 72 + eb] + xp[3];
                float cn = fsigmoid(fv) * c0 + fsigmoid(iv) * ftanh(gv);
                c0 = cn;
                float hn = fsigmoid(ov) * ftanh(cn);
                __half hbb = __float2half(hn);
                hh[eb * HH + hc0 + ej] = hbb;
                if (last) hl[eb * HH + hc0 + ej] = __float2half(hn - __half2float(hbb));
            }
            {
                int j = ej + 4;
                float iv = sg[(0 + j) * 72 + eb] + xp[4];
                float fv = sg[(8 + j) * 72 + eb] + xp[5];
                float gv = sg[(16 + j) * 72 + eb] + xp[6];
                float ov = sg[(24 + j) * 72 + eb] + xp[7];
                float cn = fsigmoid(fv) * c1 + fsigmoid(iv) * ftanh(gv);
                c1 = cn;
                float hn = fsigmoid(ov) * ftanh(cn);
                __half hbb = __float2half(hn);
                hh[eb * HH + hc0 + j] = hbb;
                if (last) hl[eb * HH + hc0 + j] = __float2half(hn - __half2float(hbb));
            }
        }
        __syncthreads();
        if (tid == 0) {
            __threadfence();                            // order h stores (gpu scope)
            atomicAdd(&g_cnt[blockIdx.x >> 4], 1u);     // signal this group's step done
        }
    }
}

// ---------------------------------------------------------------------------
// logits = h_last @ fc_w^T + fc_b; out = log_softmax.  grid=64, block=256.
// h_last = g_hhi[0] + g_hlo[0]  (full precision at the final step)
// ---------------------------------------------------------------------------
__global__ __launch_bounds__(256) void fc_kernel(const float* __restrict__ fcw,
                                                 const float* __restrict__ fcb,
                                                 float* __restrict__ out) {
    __shared__ float sh[HH];
    __shared__ float sl[64];
    __shared__ float s_red[2];
    int b = blockIdx.x;
    int tid = threadIdx.x;
    int w = tid >> 5, lane = tid & 31;

    {
        uint2 vh = ((const uint2*)(g_hhi[0] + b * HH))[tid];
        uint2 vl = ((const uint2*)(g_hlo[0] + b * HH))[tid];
        float2 h0 = unpack2h(vh.x), h1 = unpack2h(vh.y);
        float2 l0 = unpack2h(vl.x), l1 = unpack2h(vl.y);
        float4 f = make_float4(h0.x + l0.x, h0.y + l0.y, h1.x + l1.x, h1.y + l1.y);
        ((float4*)sh)[tid] = f;
    }
    __syncthreads();

#pragma unroll
    for (int cc = 0; cc < 8; cc++) {
        int c = w * 8 + cc;
        float s = 0.f;
        if (c < CC) {
            const float* wr = fcw + c * HH;
#pragma unroll 8
            for (int i = 0; i < 32; i++) {
                int k = i * 32 + lane;
                s += sh[k] * wr[k];
            }
        }
#pragma unroll
        for (int off = 16; off > 0; off >>= 1) s += __shfl_xor_sync(0xFFFFFFFF, s, off);
        if (lane == 0) sl[c] = (c < CC) ? s + fcb[c] : -1e30f;
    }
    __syncthreads();

    if (w == 0) {
        float v0 = sl[lane], v1 = sl[lane + 32];
        float m = fmaxf(v0, v1);
#pragma unroll
        for (int off = 16; off > 0; off >>= 1) m = fmaxf(m, __shfl_xor_sync(0xFFFFFFFF, m, off));
        float e = expf(v0 - m) + expf(v1 - m);
#pragma unroll
        for (int off = 16; off > 0; off >>= 1) e += __shfl_xor_sync(0xFFFFFFFF, e, off);
        if (lane == 0) { s_red[0] = m; s_red[1] = logf(e); }
    }
    __syncthreads();
    if (tid < CC) out[b * CC + tid] = sl[tid] - s_red[0] - s_red[1];
}

// ---------------------------------------------------------------------------
extern "C" void kernel_launch(void* const* d_in, const int* in_sizes, int n_in,
                              void* d_out, int out_size) {
    const float* inp = (const float*)d_in[0];   // [B,T,I]
    const float* Wih = (const float*)d_in[1];   // [4H,I]
    const float* Whh = (const float*)d_in[2];   // [4H,H]
    const float* bih = (const float*)d_in[3];   // [4H]
    const float* bhh = (const float*)d_in[4];   // [4H]
    const float* fcw = (const float*)d_in[5];   // [C,H]
    const float* fcb = (const float*)d_in[6];   // [C]
    float* out = (float*)d_out;                 // [B,C]

    cudaFuncSetAttribute(lstm_kernel, cudaFuncAttributeMaxDynamicSharedMemorySize, SMEM_DYN);
    cudaFuncSetAttribute(xproj_mma_kernel, cudaFuncAttributeMaxDynamicSharedMemorySize, SMEM_X);

    zero_kernel<<<512, 256>>>();
    conv_kernel<<<1024, 256>>>(inp, Wih);

    dim3 gx(64, 16);
    xproj_mma_kernel<<<gx, 256, SMEM_X>>>(bih, bhh);

    lstm_kernel<<<NCTA, 256, SMEM_DYN>>>(Whh);

    fc_kernel<<<BB, 64 * 4>>>(fcw, fcb, out);
}

// round 11
// speedup vs baseline: 2.2552x; 1.0843x over previous
#include <cuda_runtime.h>
#include <cuda_bf16.h>
#include <cuda_fp16.h>
#include <math.h>
#include <cstdint>

// Problem dims
constexpr int BB = 64;    // batch
constexpr int TT = 256;   // time steps
constexpr int II = 256;   // input dim
constexpr int HH = 1024;  // hidden
constexpr int CC = 60;    // classes
constexpr int GG = 4096;  // 4*H
constexpr int NCTA = 128; // persistent CTAs; each owns 8 h-cols x 4 gates = 32 gate cols

// Dynamic SMEM layout (lstm_kernel): k256 chunks, fp16 single-term
constexpr int A_B = 0;         // 2 bufs x 32KB (64 rows x 256 fp16, row=512B, block-swizzled)
constexpr int WF = 65536;      // 64KB fragment-direct W (fp16)
constexpr int SMEM_DYN = 131072;

// Dynamic SMEM layout (xproj_mma kernel): fp16 single-term
constexpr int XA = 0;          // 2 bufs x 16KB (128 rows x 64 fp16, SW128)
constexpr int XW = 32768;      // 32KB fragment-direct W_ih (fp16, 64 cols x 256 k)
constexpr int SMEM_X = 65536;

// Scratch (__device__ globals: allocation-free)
__device__ float g_xproj[(size_t)TT * BB * GG];   // [t][b][g]
__device__ __half g_hhi[2][BB * HH];              // h (fp16), ping-pong
__device__ __half g_hlo[2][BB * HH];              // h lo correction (final step only)
__device__ __half g_xh[BB * TT * II];             // inputs fp16  [(b*T+t)][i]
__device__ __half g_wih[GG * II];                 // W_ih fp16 [g][i]
__device__ unsigned g_bar;                        // single step counter

// ---------------------------------------------------------------------------
// helpers
// ---------------------------------------------------------------------------
__device__ __forceinline__ uint32_t smem_u32(const void* p) {
    uint32_t a;
    asm("{ .reg .u64 t; cvta.to.shared.u64 t, %1; cvt.u32.u64 %0, t; }" : "=r"(a) : "l"(p));
    return a;
}
__device__ __forceinline__ void ldm_x4(uint32_t* r, uint32_t addr) {
    asm volatile("ldmatrix.sync.aligned.m8n8.x4.shared.b16 {%0,%1,%2,%3}, [%4];"
                 : "=r"(r[0]), "=r"(r[1]), "=r"(r[2]), "=r"(r[3]) : "r"(addr));
}
__device__ __forceinline__ void mma_f16(float* d, const uint32_t* a, uint32_t b0, uint32_t b1) {
    asm volatile(
        "mma.sync.aligned.m16n8k16.row.col.f32.f16.f16.f32 "
        "{%0,%1,%2,%3}, {%4,%5,%6,%7}, {%8,%9}, {%0,%1,%2,%3};"
        : "+f"(d[0]), "+f"(d[1]), "+f"(d[2]), "+f"(d[3])
        : "r"(a[0]), "r"(a[1]), "r"(a[2]), "r"(a[3]), "r"(b0), "r"(b1));
}
__device__ __forceinline__ uint32_t pack2h(__half a, __half b) {
    return (uint32_t)*(uint16_t*)&a | ((uint32_t)*(uint16_t*)&b << 16);
}
__device__ __forceinline__ float2 unpack2h(uint32_t v) {
    __half2 h = *(__half2*)&v;
    return __half22float2(h);
}
__device__ __forceinline__ void poll_ge(const unsigned* p, unsigned tgt) {
    unsigned v;
    do {
        asm volatile("ld.acquire.gpu.global.u32 %0, [%1];" : "=r"(v) : "l"(p) : "memory");
    } while (v < tgt);
}
// HW tanh: single MUFU op (sm_75+); sigmoid via tanh identity (1 MUFU + 1 FFMA)
__device__ __forceinline__ float ftanh(float x) {
    float y;
    asm("tanh.approx.f32 %0, %1;" : "=f"(y) : "f"(x));
    return y;
}
__device__ __forceinline__ float fsigmoid(float x) {
    return fmaf(ftanh(0.5f * x), 0.5f, 0.5f);
}

// ---------------------------------------------------------------------------
// Zero-init h buffers + step counter.
// ---------------------------------------------------------------------------
__global__ void zero_kernel() {
    int i = blockIdx.x * blockDim.x + threadIdx.x;
    if (i < BB * HH) {            // u32 words cover both ping-pong buffers
        ((unsigned*)g_hhi)[i] = 0u;
        ((unsigned*)g_hlo)[i] = 0u;
    }
    if (i == 0) g_bar = 0u;
}

// ---------------------------------------------------------------------------
// Convert inputs and W_ih to fp16 (row-major, same layout).
// ---------------------------------------------------------------------------
__global__ void conv_kernel(const float* __restrict__ inp, const float* __restrict__ Wih) {
    int stride = gridDim.x * blockDim.x;
    int i0 = blockIdx.x * blockDim.x + threadIdx.x;
    for (int i = i0; i < 1048576; i += stride) {       // inputs: 1M float4
        float4 v = ((const float4*)inp)[i];
        uint2 h = make_uint2(pack2h(__float2half(v.x), __float2half(v.y)),
                             pack2h(__float2half(v.z), __float2half(v.w)));
        ((uint2*)g_xh)[i] = h;
    }
    for (int i = i0; i < 262144; i += stride) {        // W_ih: 256K float4
        float4 v = ((const float4*)Wih)[i];
        uint2 h = make_uint2(pack2h(__float2half(v.x), __float2half(v.y)),
                             pack2h(__float2half(v.z), __float2half(v.w)));
        ((uint2*)g_wih)[i] = h;
    }
}

// ---------------------------------------------------------------------------
// x_proj via fp16 single-term mma.sync (proven round 9).
// ---------------------------------------------------------------------------
__global__ __launch_bounds__(256, 1) void xproj_mma_kernel(
    const float* __restrict__ bih, const float* __restrict__ bhh) {
    extern __shared__ char sm[];
    const int tid = threadIdx.x;
    const int lane = tid & 31;
    const int w = tid >> 5;
    const int n0 = blockIdx.x * 64;
    const uint32_t smb = smem_u32(sm);

    // W fragment fill (8192 u32, fp16)
    for (int idx = tid; idx < 8192; idx += 256) {
        int q = idx & 15, ln = (idx >> 4) & 31, ks = idx >> 9;
        int nt = q >> 1, rr = q & 1;
        int nl = nt * 8 + (ln >> 2);
        int k = ks * 16 + rr * 8 + (ln & 3) * 2;
        ((uint32_t*)(sm + XW))[idx] = *(const uint32_t*)(g_wih + (n0 + nl) * II + k);
    }
    __syncthreads();

    const int grp = lane >> 2, tg = lane & 3;
    float bias0[8], bias1[8];
#pragma unroll
    for (int nt = 0; nt < 8; nt++) {
        int g = n0 + nt * 8 + tg * 2;
        bias0[nt] = bih[g] + bhh[g];
        bias1[nt] = bih[g + 1] + bhh[g + 1];
    }

    const int arow = w * 16 + (lane & 15);
    const int acol = (lane >> 4) * 16;

    for (int miter = 0; miter < 8; miter++) {
        const int m0 = (blockIdx.y * 8 + miter) * 128;

        float acc[8][4];
#pragma unroll
        for (int z = 0; z < 8; z++)
#pragma unroll
            for (int r = 0; r < 4; r++) acc[z][r] = 0.f;

        // prologue: chunk 0 -> buf 0 (4 x 16B segments per thread)
#pragma unroll
        for (int i = 0; i < 4; i++) {
            int s = i * 256 + tid;
            int row = s >> 3, sb = s & 7;
            uint4 v = ((const uint4*)g_xh)[(m0 + row) * 32 + sb];
            int off = row * 128 + sb * 16;
            int sw = off ^ ((off >> 3) & 0x70);
            *(uint4*)(sm + XA + sw) = v;
        }
        __syncthreads();

        for (int ch = 0; ch < 4; ch++) {
            const int buf = ch & 1;
            uint4 ph[4];
            if (ch < 3) {
#pragma unroll
                for (int i = 0; i < 4; i++) {
                    int s = i * 256 + tid;
                    int row = s >> 3, sb = s & 7;
                    ph[i] = ((const uint4*)g_xh)[(m0 + row) * 32 + (ch + 1) * 8 + sb];
                }
            }
            const uint32_t ab = smb + XA + buf * 16384;
#pragma unroll
            for (int kl = 0; kl < 4; kl++) {
                const int ks = ch * 4 + kl;
                int off = arow * 128 + kl * 32 + acol;
                int sw = off ^ ((off >> 3) & 0x70);
                uint32_t ah[4];
                ldm_x4(ah, ab + sw);
                const uint4* wh4 = (const uint4*)(sm + XW) + (ks * 32 + lane) * 4;
#pragma unroll
                for (int q4 = 0; q4 < 4; q4++) {
                    uint4 bh = wh4[q4];
                    mma_f16(acc[2 * q4], ah, bh.x, bh.y);
                    mma_f16(acc[2 * q4 + 1], ah, bh.z, bh.w);
                }
            }
            if (ch < 3) {
                char* dh = sm + XA + (buf ^ 1) * 16384;
#pragma unroll
                for (int i = 0; i < 4; i++) {
                    int s = i * 256 + tid;
                    int row = s >> 3, sb = s & 7;
                    int off = row * 128 + sb * 16;
                    int sw = off ^ ((off >> 3) & 0x70);
                    *(uint4*)(dh + sw) = ph[i];
                }
            }
            __syncthreads();
        }

        int r0 = m0 + w * 16 + grp;
        int r1 = r0 + 8;
        size_t ob0 = ((size_t)(r0 & 255) * BB + (r0 >> 8)) * GG;
        size_t ob1 = ((size_t)(r1 & 255) * BB + (r1 >> 8)) * GG;
#pragma unroll
        for (int nt = 0; nt < 8; nt++) {
            int g = n0 + nt * 8 + tg * 2;
            float2 v0 = make_float2(acc[nt][0] + bias0[nt], acc[nt][1] + bias1[nt]);
            float2 v1 = make_float2(acc[nt][2] + bias0[nt], acc[nt][3] + bias1[nt]);
            *(float2*)&g_xproj[ob0 + g] = v0;
            *(float2*)&g_xproj[ob1 + g] = v1;
        }
    }
}

// ---------------------------------------------------------------------------
// Persistent LSTM recurrence: 128 CTAs x 256 thr.  fp16 single-term.
// NEW: k256 chunks (4/step), single step counter, one poll per step,
// 7 syncthreads per step.  A row = 512B, block-local XOR swizzle.
// ---------------------------------------------------------------------------
__global__ __launch_bounds__(256, 1) void lstm_kernel(const float* __restrict__ Whh) {
    extern __shared__ char sm[];
    const int tid = threadIdx.x;
    const int lane = tid & 31;
    const int w = tid >> 5;
    const int mt = w & 3, nh = w >> 2;
    const int hc0 = blockIdx.x * 8;
    const uint32_t smb = smem_u32(sm);

    // ---- one-time: W fragment fill (fp16, fragment-direct layout) ----
    for (int idx = tid; idx < 16384; idx += 256) {
        int r = idx & 3, ln = (idx >> 2) & 31, ks = (idx >> 7) & 63, nhh = idx >> 13;
        int nt = r >> 1;
        int kk = (r & 1) * 8 + (ln & 3) * 2;
        int nl = nhh * 16 + nt * 8 + (ln >> 2);
        int k = ks * 16 + kk;
        int gr = (nl >> 3) * 1024 + hc0 + (nl & 7);
        __half h0 = __float2half(Whh[gr * 1024 + k]);
        __half h1 = __float2half(Whh[gr * 1024 + k + 1]);
        ((uint32_t*)(sm + WF))[idx] = pack2h(h0, h1);
    }
    __syncthreads();

    // staging constants: thread handles 8 x 16B segments per chunk
    // A buf: 64 rows x 512B; row = 4 blocks of 128B; swizzle inner^(row&7)
    int ssw[8], sgix[8];
#pragma unroll
    for (int i = 0; i < 8; i++) {
        int s = i * 256 + tid;                  // 0..2047
        int row = s >> 5, seg = s & 31;
        int block = seg >> 3, inner = seg & 7;
        ssw[i] = row * 512 + block * 128 + ((inner ^ (row & 7)) << 4);
        sgix[i] = row * 128 + seg;              // + ch*32 per chunk (uint4 units)
    }

    // A ldmatrix per-lane constants
    const int arow = mt * 16 + (lane & 15);
    const int ahalf = lane >> 4;                // k-half within kstep

    // epilogue ownership: this thread handles states (b, ej) and (b, ej+4)
    const int eb = tid & 63, ej = tid >> 6;
    float c0 = 0.f, c1 = 0.f;

    for (int t = 0; t < TT; t++) {
        const uint4* gh = (const uint4*)g_hhi[t & 1];
        const float* xg = g_xproj + (size_t)t * BB * GG;

        // wait once for all CTAs to have finished step t-1
        if (t) {
            if (lane == 0) poll_ge(&g_bar, (unsigned)NCTA * t);
            __syncwarp();
        }

        // prefetch this thread's xproj values (4 gates x 2 states)
        float xp[8];
#pragma unroll
        for (int q = 0; q < 4; q++) {
            xp[q] = xg[(size_t)eb * GG + q * HH + hc0 + ej];
            xp[4 + q] = xg[(size_t)eb * GG + q * HH + hc0 + ej + 4];
        }

        float acc[4][4];    // [ (kl&1)*2 + nt ][4] : 4 independent chains
#pragma unroll
        for (int z = 0; z < 4; z++)
#pragma unroll
            for (int r = 0; r < 4; r++) acc[z][r] = 0.f;

        // prologue: stage chunk 0 -> buf 0
        {
            uint4 vh[8];
#pragma unroll
            for (int i = 0; i < 8; i++) vh[i] = __ldcg(gh + sgix[i]);
#pragma unroll
            for (int i = 0; i < 8; i++) *(uint4*)(sm + A_B + ssw[i]) = vh[i];
        }
        __syncthreads();

        for (int ch = 0; ch < 4; ch++) {
            const int buf = ch & 1;
            uint4 ph[8];
            if (ch < 3) {
#pragma unroll
                for (int i = 0; i < 8; i++) ph[i] = __ldcg(gh + sgix[i] + (ch + 1) * 32);
            }
            const uint32_t ab = smb + A_B + buf * 32768;
            const uint4* wf = (const uint4*)(sm + WF) + ((nh * 64 + ch * 16) * 32 + lane);
#pragma unroll
            for (int kl = 0; kl < 16; kl++) {
                int seg = kl * 2 + ahalf;
                int block = seg >> 3, inner = seg & 7;
                int sw = arow * 512 + block * 128 + ((inner ^ (arow & 7)) << 4);
                uint32_t ah[4];
                ldm_x4(ah, ab + sw);
                uint4 bh = wf[kl * 32];
                int z = (kl & 1) * 2;
                mma_f16(acc[z], ah, bh.x, bh.y);
                mma_f16(acc[z + 1], ah, bh.z, bh.w);
            }
            if (ch < 3) {
                char* dh = sm + A_B + (buf ^ 1) * 32768;
#pragma unroll
                for (int i = 0; i < 8; i++) *(uint4*)(dh + ssw[i]) = ph[i];
            }
            __syncthreads();
        }

        // epilogue: exchange D fragments via SMEM [32 cols][stride 72]
        float* sg = (float*)sm;
        {
            int grp = lane >> 2, tg = lane & 3;
#pragma unroll
            for (int nt = 0; nt < 2; nt++) {
                int col = nh * 16 + nt * 8 + tg * 2;
                int row = mt * 16 + grp;
                sg[col * 72 + row] = acc[nt][0] + acc[2 + nt][0];
                sg[(col + 1) * 72 + row] = acc[nt][1] + acc[2 + nt][1];
                sg[col * 72 + row + 8] = acc[nt][2] + acc[2 + nt][2];
                sg[(col + 1) * 72 + row + 8] = acc[nt][3] + acc[2 + nt][3];
            }
        }
        __syncthreads();

        // pointwise update (HW tanh): 512 states over 256 threads (2 each)
        {
            __half* hh = g_hhi[(t + 1) & 1];
            __half* hl = g_hlo[(t + 1) & 1];
            const bool last = (t == TT - 1);
            {
                float iv = sg[(0 + ej) * 72 + eb] + xp[0];
                float fv = sg[(8 + ej) * 72 + eb] + xp[1];
                float gv = sg[(16 + ej) * 72 + eb] + xp[2];
                float ov = sg[(24 + ej) * 72 + eb] + xp[3];
                float cn = fsigmoid(fv) * c0 + fsigmoid(iv) * ftanh(gv);
                c0 = cn;
                float hn = fsigmoid(ov) * ftanh(cn);
                __half hbb = __float2half(hn);
                hh[eb * HH + hc0 + ej] = hbb;
                if (last) hl[eb * HH + hc0 + ej] = __float2half(hn - __half2float(hbb));
            }
            {
                int j = ej + 4;
                float iv = sg[(0 + j) * 72 + eb] + xp[4];
                float fv = sg[(8 + j) * 72 + eb] + xp[5];
                float gv = sg[(16 + j) * 72 + eb] + xp[6];
                float ov = sg[(24 + j) * 72 + eb] + xp[7];
                float cn = fsigmoid(fv) * c1 + fsigmoid(iv) * ftanh(gv);
                c1 = cn;
                float hn = fsigmoid(ov) * ftanh(cn);
                __half hbb = __float2half(hn);
                hh[eb * HH + hc0 + j] = hbb;
                if (last) hl[eb * HH + hc0 + j] = __float2half(hn - __half2float(hbb));
            }
        }
        __syncthreads();
        if (tid == 0) {
            __threadfence();                // order h stores (gpu scope)
            atomicAdd(&g_bar, 1u);          // signal this CTA's step done
        }
    }
}

// ---------------------------------------------------------------------------
// logits = h_last @ fc_w^T + fc_b; out = log_softmax.  grid=64, block=256.
// h_last = g_hhi[0] + g_hlo[0]  (full precision at the final step)
// ---------------------------------------------------------------------------
__global__ __launch_bounds__(256) void fc_kernel(const float* __restrict__ fcw,
                                                 const float* __restrict__ fcb,
                                                 float* __restrict__ out) {
    __shared__ float sh[HH];
    __shared__ float sl[64];
    __shared__ float s_red[2];
    int b = blockIdx.x;
    int tid = threadIdx.x;
    int w = tid >> 5, lane = tid & 31;

    {
        uint2 vh = ((const uint2*)(g_hhi[0] + b * HH))[tid];
        uint2 vl = ((const uint2*)(g_hlo[0] + b * HH))[tid];
        float2 h0 = unpack2h(vh.x), h1 = unpack2h(vh.y);
        float2 l0 = unpack2h(vl.x), l1 = unpack2h(vl.y);
        float4 f = make_float4(h0.x + l0.x, h0.y + l0.y, h1.x + l1.x, h1.y + l1.y);
        ((float4*)sh)[tid] = f;
    }
    __syncthreads();

#pragma unroll
    for (int cc = 0; cc < 8; cc++) {
        int c = w * 8 + cc;
        float s = 0.f;
        if (c < CC) {
            const float* wr = fcw + c * HH;
#pragma unroll 8
            for (int i = 0; i < 32; i++) {
                int k = i * 32 + lane;
                s += sh[k] * wr[k];
            }
        }
#pragma unroll
        for (int off = 16; off > 0; off >>= 1) s += __shfl_xor_sync(0xFFFFFFFF, s, off);
        if (lane == 0) sl[c] = (c < CC) ? s + fcb[c] : -1e30f;
    }
    __syncthreads();

    if (w == 0) {
        float v0 = sl[lane], v1 = sl[lane + 32];
        float m = fmaxf(v0, v1);
#pragma unroll
        for (int off = 16; off > 0; off >>= 1) m = fmaxf(m, __shfl_xor_sync(0xFFFFFFFF, m, off));
        float e = expf(v0 - m) + expf(v1 - m);
#pragma unroll
        for (int off = 16; off > 0; off >>= 1) e += __shfl_xor_sync(0xFFFFFFFF, e, off);
        if (lane == 0) { s_red[0] = m; s_red[1] = logf(e); }
    }
    __syncthreads();
    if (tid < CC) out[b * CC + tid] = sl[tid] - s_red[0] - s_red[1];
}

// ---------------------------------------------------------------------------
extern "C" void kernel_launch(void* const* d_in, const int* in_sizes, int n_in,
                              void* d_out, int out_size) {
    const float* inp = (const float*)d_in[0];   // [B,T,I]
    const float* Wih = (const float*)d_in[1];   // [4H,I]
    const float* Whh = (const float*)d_in[2];   // [4H,H]
    const float* bih = (const float*)d_in[3];   // [4H]
    const float* bhh = (const float*)d_in[4];   // [4H]
    const float* fcw = (const float*)d_in[5];   // [C,H]
    const float* fcb = (const float*)d_in[6];   // [C]
    float* out = (float*)d_out;                 // [B,C]

    cudaFuncSetAttribute(lstm_kernel, cudaFuncAttributeMaxDynamicSharedMemorySize, SMEM_DYN);
    cudaFuncSetAttribute(xproj_mma_kernel, cudaFuncAttributeMaxDynamicSharedMemorySize, SMEM_X);

    zero_kernel<<<512, 256>>>();
    conv_kernel<<<1024, 256>>>(inp, Wih);

    dim3 gx(64, 16);
    xproj_mma_kernel<<<gx, 256, SMEM_X>>>(bih, bhh);

    lstm_kernel<<<NCTA, 256, SMEM_DYN>>>(Whh);

    fc_kernel<<<BB, 64 * 4>>>(fcw, fcb, out);
}

// round 12
// speedup vs baseline: 2.7044x; 1.1992x over previous
#include <cuda_runtime.h>
#include <cuda_bf16.h>
#include <cuda_fp16.h>
#include <math.h>
#include <cstdint>

// Problem dims
constexpr int BB = 64;    // batch
constexpr int TT = 256;   // time steps
constexpr int II = 256;   // input dim
constexpr int HH = 1024;  // hidden
constexpr int CC = 60;    // classes
constexpr int GG = 4096;  // 4*H
constexpr int NCTA = 128; // persistent CTAs; each owns 8 h-cols x 4 gates = 32 gate cols

// Dynamic SMEM layout (lstm_kernel): k256 chunks, fp16 single-term
constexpr int A_B = 0;         // 2 bufs x 32KB (64 rows x 256 fp16, row=512B, block-swizzled)
constexpr int WF = 65536;      // 64KB fragment-direct W (fp16)
constexpr int XP = 131072;     // 9216B xproj bounce [64][36] fp32 (pad 36 -> 4-way LDS max)
constexpr int SMEM_DYN = 140288;

// Dynamic SMEM layout (xproj_mma kernel): fp16 single-term
constexpr int XA = 0;          // 2 bufs x 16KB (128 rows x 64 fp16, SW128)
constexpr int XW = 32768;      // 32KB fragment-direct W_ih (fp16, 64 cols x 256 k)
constexpr int SMEM_X = 65536;

// Scratch (__device__ globals: allocation-free)
__device__ float g_xproj[(size_t)TT * BB * GG];   // [t][b][g]
__device__ __half g_hhi[2][BB * HH];              // h (fp16), ping-pong
__device__ __half g_hlo[2][BB * HH];              // h lo correction (final step only)
__device__ __half g_xh[BB * TT * II];             // inputs fp16  [(b*T+t)][i]
__device__ __half g_wih[GG * II];                 // W_ih fp16 [g][i]
__device__ unsigned g_bar;                        // single step counter

// ---------------------------------------------------------------------------
// helpers
// ---------------------------------------------------------------------------
__device__ __forceinline__ uint32_t smem_u32(const void* p) {
    uint32_t a;
    asm("{ .reg .u64 t; cvta.to.shared.u64 t, %1; cvt.u32.u64 %0, t; }" : "=r"(a) : "l"(p));
    return a;
}
__device__ __forceinline__ void ldm_x4(uint32_t* r, uint32_t addr) {
    asm volatile("ldmatrix.sync.aligned.m8n8.x4.shared.b16 {%0,%1,%2,%3}, [%4];"
                 : "=r"(r[0]), "=r"(r[1]), "=r"(r[2]), "=r"(r[3]) : "r"(addr));
}
__device__ __forceinline__ void mma_f16(float* d, const uint32_t* a, uint32_t b0, uint32_t b1) {
    asm volatile(
        "mma.sync.aligned.m16n8k16.row.col.f32.f16.f16.f32 "
        "{%0,%1,%2,%3}, {%4,%5,%6,%7}, {%8,%9}, {%0,%1,%2,%3};"
        : "+f"(d[0]), "+f"(d[1]), "+f"(d[2]), "+f"(d[3])
        : "r"(a[0]), "r"(a[1]), "r"(a[2]), "r"(a[3]), "r"(b0), "r"(b1));
}
__device__ __forceinline__ uint32_t pack2h(__half a, __half b) {
    return (uint32_t)*(uint16_t*)&a | ((uint32_t)*(uint16_t*)&b << 16);
}
__device__ __forceinline__ float2 unpack2h(uint32_t v) {
    __half2 h = *(__half2*)&v;
    return __half22float2(h);
}
__device__ __forceinline__ void poll_ge(const unsigned* p, unsigned tgt) {
    unsigned v;
    do {
        asm volatile("ld.acquire.gpu.global.u32 %0, [%1];" : "=r"(v) : "l"(p) : "memory");
    } while (v < tgt);
}
// HW tanh: single MUFU op (sm_75+); sigmoid via tanh identity (1 MUFU + 1 FFMA)
__device__ __forceinline__ float ftanh(float x) {
    float y;
    asm("tanh.approx.f32 %0, %1;" : "=f"(y) : "f"(x));
    return y;
}
__device__ __forceinline__ float fsigmoid(float x) {
    return fmaf(ftanh(0.5f * x), 0.5f, 0.5f);
}

// ---------------------------------------------------------------------------
// Zero-init h buffers + step counter.
// ---------------------------------------------------------------------------
__global__ void zero_kernel() {
    int i = blockIdx.x * blockDim.x + threadIdx.x;
    if (i < BB * HH) {            // u32 words cover both ping-pong buffers
        ((unsigned*)g_hhi)[i] = 0u;
        ((unsigned*)g_hlo)[i] = 0u;
    }
    if (i == 0) g_bar = 0u;
}

// ---------------------------------------------------------------------------
// Convert inputs and W_ih to fp16 (row-major, same layout).
// ---------------------------------------------------------------------------
__global__ void conv_kernel(const float* __restrict__ inp, const float* __restrict__ Wih) {
    int stride = gridDim.x * blockDim.x;
    int i0 = blockIdx.x * blockDim.x + threadIdx.x;
    for (int i = i0; i < 1048576; i += stride) {       // inputs: 1M float4
        float4 v = ((const float4*)inp)[i];
        uint2 h = make_uint2(pack2h(__float2half(v.x), __float2half(v.y)),
                             pack2h(__float2half(v.z), __float2half(v.w)));
        ((uint2*)g_xh)[i] = h;
    }
    for (int i = i0; i < 262144; i += stride) {        // W_ih: 256K float4
        float4 v = ((const float4*)Wih)[i];
        uint2 h = make_uint2(pack2h(__float2half(v.x), __float2half(v.y)),
                             pack2h(__float2half(v.z), __float2half(v.w)));
        ((uint2*)g_wih)[i] = h;
    }
}

// ---------------------------------------------------------------------------
// x_proj via fp16 single-term mma.sync (proven round 9).
// ---------------------------------------------------------------------------
__global__ __launch_bounds__(256, 1) void xproj_mma_kernel(
    const float* __restrict__ bih, const float* __restrict__ bhh) {
    extern __shared__ char sm[];
    const int tid = threadIdx.x;
    const int lane = tid & 31;
    const int w = tid >> 5;
    const int n0 = blockIdx.x * 64;
    const uint32_t smb = smem_u32(sm);

    // W fragment fill (8192 u32, fp16)
    for (int idx = tid; idx < 8192; idx += 256) {
        int q = idx & 15, ln = (idx >> 4) & 31, ks = idx >> 9;
        int nt = q >> 1, rr = q & 1;
        int nl = nt * 8 + (ln >> 2);
        int k = ks * 16 + rr * 8 + (ln & 3) * 2;
        ((uint32_t*)(sm + XW))[idx] = *(const uint32_t*)(g_wih + (n0 + nl) * II + k);
    }
    __syncthreads();

    const int grp = lane >> 2, tg = lane & 3;
    float bias0[8], bias1[8];
#pragma unroll
    for (int nt = 0; nt < 8; nt++) {
        int g = n0 + nt * 8 + tg * 2;
        bias0[nt] = bih[g] + bhh[g];
        bias1[nt] = bih[g + 1] + bhh[g + 1];
    }

    const int arow = w * 16 + (lane & 15);
    const int acol = (lane >> 4) * 16;

    for (int miter = 0; miter < 8; miter++) {
        const int m0 = (blockIdx.y * 8 + miter) * 128;

        float acc[8][4];
#pragma unroll
        for (int z = 0; z < 8; z++)
#pragma unroll
            for (int r = 0; r < 4; r++) acc[z][r] = 0.f;

        // prologue: chunk 0 -> buf 0 (4 x 16B segments per thread)
#pragma unroll
        for (int i = 0; i < 4; i++) {
            int s = i * 256 + tid;
            int row = s >> 3, sb = s & 7;
            uint4 v = ((const uint4*)g_xh)[(m0 + row) * 32 + sb];
            int off = row * 128 + sb * 16;
            int sw = off ^ ((off >> 3) & 0x70);
            *(uint4*)(sm + XA + sw) = v;
        }
        __syncthreads();

        for (int ch = 0; ch < 4; ch++) {
            const int buf = ch & 1;
            uint4 ph[4];
            if (ch < 3) {
#pragma unroll
                for (int i = 0; i < 4; i++) {
                    int s = i * 256 + tid;
                    int row = s >> 3, sb = s & 7;
                    ph[i] = ((const uint4*)g_xh)[(m0 + row) * 32 + (ch + 1) * 8 + sb];
                }
            }
            const uint32_t ab = smb + XA + buf * 16384;
#pragma unroll
            for (int kl = 0; kl < 4; kl++) {
                const int ks = ch * 4 + kl;
                int off = arow * 128 + kl * 32 + acol;
                int sw = off ^ ((off >> 3) & 0x70);
                uint32_t ah[4];
                ldm_x4(ah, ab + sw);
                const uint4* wh4 = (const uint4*)(sm + XW) + (ks * 32 + lane) * 4;
#pragma unroll
                for (int q4 = 0; q4 < 4; q4++) {
                    uint4 bh = wh4[q4];
                    mma_f16(acc[2 * q4], ah, bh.x, bh.y);
                    mma_f16(acc[2 * q4 + 1], ah, bh.z, bh.w);
                }
            }
            if (ch < 3) {
                char* dh = sm + XA + (buf ^ 1) * 16384;
#pragma unroll
                for (int i = 0; i < 4; i++) {
                    int s = i * 256 + tid;
                    int row = s >> 3, sb = s & 7;
                    int off = row * 128 + sb * 16;
                    int sw = off ^ ((off >> 3) & 0x70);
                    *(uint4*)(dh + sw) = ph[i];
                }
            }
            __syncthreads();
        }

        int r0 = m0 + w * 16 + grp;
        int r1 = r0 + 8;
        size_t ob0 = ((size_t)(r0 & 255) * BB + (r0 >> 8)) * GG;
        size_t ob1 = ((size_t)(r1 & 255) * BB + (r1 >> 8)) * GG;
#pragma unroll
        for (int nt = 0; nt < 8; nt++) {
            int g = n0 + nt * 8 + tg * 2;
            float2 v0 = make_float2(acc[nt][0] + bias0[nt], acc[nt][1] + bias1[nt]);
            float2 v1 = make_float2(acc[nt][2] + bias0[nt], acc[nt][3] + bias1[nt]);
            *(float2*)&g_xproj[ob0 + g] = v0;
            *(float2*)&g_xproj[ob1 + g] = v1;
        }
    }
}

// ---------------------------------------------------------------------------
// Persistent LSTM recurrence: 128 CTAs x 256 thr.  fp16 single-term.
// R11 skeleton (k256 chunks x 4, single counter) + NEW coalesced xproj
// bounce staged BEFORE the barrier poll (cuts ~1.5k L1 wavefronts/step
// and removes the scatter from the critical path).
// ---------------------------------------------------------------------------
__global__ __launch_bounds__(256, 1) void lstm_kernel(const float* __restrict__ Whh) {
    extern __shared__ char sm[];
    const int tid = threadIdx.x;
    const int lane = tid & 31;
    const int w = tid >> 5;
    const int mt = w & 3, nh = w >> 2;
    const int hc0 = blockIdx.x * 8;
    const uint32_t smb = smem_u32(sm);

    // ---- one-time: W fragment fill (fp16, fragment-direct layout) ----
    for (int idx = tid; idx < 16384; idx += 256) {
        int r = idx & 3, ln = (idx >> 2) & 31, ks = (idx >> 7) & 63, nhh = idx >> 13;
        int nt = r >> 1;
        int kk = (r & 1) * 8 + (ln & 3) * 2;
        int nl = nhh * 16 + nt * 8 + (ln >> 2);
        int k = ks * 16 + kk;
        int gr = (nl >> 3) * 1024 + hc0 + (nl & 7);
        __half h0 = __float2half(Whh[gr * 1024 + k]);
        __half h1 = __float2half(Whh[gr * 1024 + k + 1]);
        ((uint32_t*)(sm + WF))[idx] = pack2h(h0, h1);
    }
    __syncthreads();

    // staging constants: thread handles 8 x 16B segments per chunk
    // A buf: 64 rows x 512B; row = 4 blocks of 128B; swizzle inner^(row&7)
    int ssw[8], sgix[8];
#pragma unroll
    for (int i = 0; i < 8; i++) {
        int s = i * 256 + tid;                  // 0..2047
        int row = s >> 5, seg = s & 31;
        int block = seg >> 3, inner = seg & 7;
        ssw[i] = row * 512 + block * 128 + ((inner ^ (row & 7)) << 4);
        sgix[i] = row * 128 + seg;              // + ch*32 per chunk (uint4 units)
    }

    // xproj loader constants: thread loads (b=tid&63, q=tid>>6) 8 floats
    const int xlb = tid & 63, xlq = tid >> 6;
    const float* xsrc0 = g_xproj + (size_t)xlb * GG + xlq * HH + hc0;
    float* const xps = (float*)(sm + XP);

    // A ldmatrix per-lane constants
    const int arow = mt * 16 + (lane & 15);
    const int ahalf = lane >> 4;                // k-half within kstep

    // epilogue ownership: this thread handles states (b, ej) and (b, ej+4)
    const int eb = tid & 63, ej = tid >> 6;
    float c0 = 0.f, c1 = 0.f;

    for (int t = 0; t < TT; t++) {
        const uint4* gh = (const uint4*)g_hhi[t & 1];

        // stage this CTA's xproj slice (coalesced, h-independent): BEFORE poll
        {
            const float* src = xsrc0 + (size_t)t * BB * GG;
            float4 xv0 = *(const float4*)(src);
            float4 xv1 = *(const float4*)(src + 4);
            *(float4*)(xps + xlb * 36 + xlq * 8) = xv0;
            *(float4*)(xps + xlb * 36 + xlq * 8 + 4) = xv1;
        }

        // wait once for all CTAs to have finished step t-1
        if (t) {
            if (lane == 0) poll_ge(&g_bar, (unsigned)NCTA * t);
            __syncwarp();
        }

        float acc[4][4];    // [ (kl&1)*2 + nt ][4] : 4 independent chains
#pragma unroll
        for (int z = 0; z < 4; z++)
#pragma unroll
            for (int r = 0; r < 4; r++) acc[z][r] = 0.f;

        // prologue: stage chunk 0 -> buf 0
        {
            uint4 vh[8];
#pragma unroll
            for (int i = 0; i < 8; i++) vh[i] = __ldcg(gh + sgix[i]);
#pragma unroll
            for (int i = 0; i < 8; i++) *(uint4*)(sm + A_B + ssw[i]) = vh[i];
        }
        __syncthreads();

        for (int ch = 0; ch < 4; ch++) {
            const int buf = ch & 1;
            uint4 ph[8];
            if (ch < 3) {
#pragma unroll
                for (int i = 0; i < 8; i++) ph[i] = __ldcg(gh + sgix[i] + (ch + 1) * 32);
            }
            const uint32_t ab = smb + A_B + buf * 32768;
            const uint4* wf = (const uint4*)(sm + WF) + ((nh * 64 + ch * 16) * 32 + lane);
#pragma unroll
            for (int kl = 0; kl < 16; kl++) {
                int seg = kl * 2 + ahalf;
                int block = seg >> 3, inner = seg & 7;
                int sw = arow * 512 + block * 128 + ((inner ^ (arow & 7)) << 4);
                uint32_t ah[4];
                ldm_x4(ah, ab + sw);
                uint4 bh = wf[kl * 32];
                int z = (kl & 1) * 2;
                mma_f16(acc[z], ah, bh.x, bh.y);
                mma_f16(acc[z + 1], ah, bh.z, bh.w);
            }
            if (ch < 3) {
                char* dh = sm + A_B + (buf ^ 1) * 32768;
#pragma unroll
                for (int i = 0; i < 8; i++) *(uint4*)(dh + ssw[i]) = ph[i];
            }
            __syncthreads();
        }

        // epilogue: exchange D fragments via SMEM [32 cols][stride 72]
        float* sg = (float*)sm;
        {
            int grp = lane >> 2, tg = lane & 3;
#pragma unroll
            for (int nt = 0; nt < 2; nt++) {
                int col = nh * 16 + nt * 8 + tg * 2;
                int row = mt * 16 + grp;
                sg[col * 72 + row] = acc[nt][0] + acc[2 + nt][0];
                sg[(col + 1) * 72 + row] = acc[nt][1] + acc[2 + nt][1];
                sg[col * 72 + row + 8] = acc[nt][2] + acc[2 + nt][2];
                sg[(col + 1) * 72 + row + 8] = acc[nt][3] + acc[2 + nt][3];
            }
        }
        __syncthreads();

        // pointwise update (HW tanh): 512 states over 256 threads (2 each)
        {
            __half* hh = g_hhi[(t + 1) & 1];
            __half* hl = g_hlo[(t + 1) & 1];
            const bool last = (t == TT - 1);
            const float* xb = xps + eb * 36;
            {
                float iv = sg[(0 + ej) * 72 + eb] + xb[0 * 8 + ej];
                float fv = sg[(8 + ej) * 72 + eb] + xb[1 * 8 + ej];
                float gv = sg[(16 + ej) * 72 + eb] + xb[2 * 8 + ej];
                float ov = sg[(24 + ej) * 72 + eb] + xb[3 * 8 + ej];
                float cn = fsigmoid(fv) * c0 + fsigmoid(iv) * ftanh(gv);
                c0 = cn;
                float hn = fsigmoid(ov) * ftanh(cn);
                __half hbb = __float2half(hn);
                hh[eb * HH + hc0 + ej] = hbb;
                if (last) hl[eb * HH + hc0 + ej] = __float2half(hn - __half2float(hbb));
            }
            {
                int j = ej + 4;
                float iv = sg[(0 + j) * 72 + eb] + xb[0 * 8 + j];
                float fv = sg[(8 + j) * 72 + eb] + xb[1 * 8 + j];
                float gv = sg[(16 + j) * 72 + eb] + xb[2 * 8 + j];
                float ov = sg[(24 + j) * 72 + eb] + xb[3 * 8 + j];
                float cn = fsigmoid(fv) * c1 + fsigmoid(iv) * ftanh(gv);
                c1 = cn;
                float hn = fsigmoid(ov) * ftanh(cn);
                __half hbb = __float2half(hn);
                hh[eb * HH + hc0 + j] = hbb;
                if (last) hl[eb * HH + hc0 + j] = __float2half(hn - __half2float(hbb));
            }
        }
        __syncthreads();
        if (tid == 0) {
            __threadfence();                // order h stores (gpu scope)
            atomicAdd(&g_bar, 1u);          // signal this CTA's step done
        }
    }
}

// ---------------------------------------------------------------------------
// logits = h_last @ fc_w^T + fc_b; out = log_softmax.  grid=64, block=256.
// h_last = g_hhi[0] + g_hlo[0]  (full precision at the final step)
// ---------------------------------------------------------------------------
__global__ __launch_bounds__(256) void fc_kernel(const float* __restrict__ fcw,
                                                 const float* __restrict__ fcb,
                                                 float* __restrict__ out) {
    __shared__ float sh[HH];
    __shared__ float sl[64];
    __shared__ float s_red[2];
    int b = blockIdx.x;
    int tid = threadIdx.x;
    int w = tid >> 5, lane = tid & 31;

    {
        uint2 vh = ((const uint2*)(g_hhi[0] + b * HH))[tid];
        uint2 vl = ((const uint2*)(g_hlo[0] + b * HH))[tid];
        float2 h0 = unpack2h(vh.x), h1 = unpack2h(vh.y);
        float2 l0 = unpack2h(vl.x), l1 = unpack2h(vl.y);
        float4 f = make_float4(h0.x + l0.x, h0.y + l0.y, h1.x + l1.x, h1.y + l1.y);
        ((float4*)sh)[tid] = f;
    }
    __syncthreads();

#pragma unroll
    for (int cc = 0; cc < 8; cc++) {
        int c = w * 8 + cc;
        float s = 0.f;
        if (c < CC) {
            const float* wr = fcw + c * HH;
#pragma unroll 8
            for (int i = 0; i < 32; i++) {
                int k = i * 32 + lane;
                s += sh[k] * wr[k];
            }
        }
#pragma unroll
        for (int off = 16; off > 0; off >>= 1) s += __shfl_xor_sync(0xFFFFFFFF, s, off);
        if (lane == 0) sl[c] = (c < CC) ? s + fcb[c] : -1e30f;
    }
    __syncthreads();

    if (w == 0) {
        float v0 = sl[lane], v1 = sl[lane + 32];
        float m = fmaxf(v0, v1);
#pragma unroll
        for (int off = 16; off > 0; off >>= 1) m = fmaxf(m, __shfl_xor_sync(0xFFFFFFFF, m, off));
        float e = expf(v0 - m) + expf(v1 - m);
#pragma unroll
        for (int off = 16; off > 0; off >>= 1) e += __shfl_xor_sync(0xFFFFFFFF, e, off);
        if (lane == 0) { s_red[0] = m; s_red[1] = logf(e); }
    }
    __syncthreads();
    if (tid < CC) out[b * CC + tid] = sl[tid] - s_red[0] - s_red[1];
}

// ---------------------------------------------------------------------------
extern "C" void kernel_launch(void* const* d_in, const int* in_sizes, int n_in,
                              void* d_out, int out_size) {
    const float* inp = (const float*)d_in[0];   // [B,T,I]
    const float* Wih = (const float*)d_in[1];   // [4H,I]
    const float* Whh = (const float*)d_in[2];   // [4H,H]
    const float* bih = (const float*)d_in[3];   // [4H]
    const float* bhh = (const float*)d_in[4];   // [4H]
    const float* fcw = (const float*)d_in[5];   // [C,H]
    const float* fcb = (const float*)d_in[6];   // [C]
    float* out = (float*)d_out;                 // [B,C]

    cudaFuncSetAttribute(lstm_kernel, cudaFuncAttributeMaxDynamicSharedMemorySize, SMEM_DYN);
    cudaFuncSetAttribute(xproj_mma_kernel, cudaFuncAttributeMaxDynamicSharedMemorySize, SMEM_X);

    zero_kernel<<<512, 256>>>();
    conv_kernel<<<1024, 256>>>(inp, Wih);

    dim3 gx(64, 16);
    xproj_mma_kernel<<<gx, 256, SMEM_X>>>(bih, bhh);

    lstm_kernel<<<NCTA, 256, SMEM_DYN>>>(Whh);

    fc_kernel<<<BB, 64 * 4>>>(fcw, fcb, out);
}

// round 13
// speedup vs baseline: 2.8675x; 1.0603x over previous
#include <cuda_runtime.h>
#include <cuda_bf16.h>
#include <cuda_fp16.h>
#include <math.h>
#include <cstdint>

// Problem dims
constexpr int BB = 64;    // batch
constexpr int TT = 256;   // time steps
constexpr int II = 256;   // input dim
constexpr int HH = 1024;  // hidden
constexpr int CC = 60;    // classes
constexpr int GG = 4096;  // 4*H
constexpr int NCTA = 128; // persistent CTAs; each owns 8 h-cols x 4 gates = 32 gate cols

// Dynamic SMEM layout (lstm_kernel): warp-per-chunk, single A buffer
constexpr int A_B = 0;         // 128KB: full h, 64 rows x 2048B, block-swizzled
                               // (overlaid by 4 x 9216B exchange regions post-MMA)
constexpr int WF = 131072;     // 64KB fragment-direct W (fp16)
constexpr int XP = 196608;     // 9216B xproj bounce [64][36] fp32
constexpr int SMEM_DYN = 205824;

// Dynamic SMEM layout (xproj_mma kernel): fp16 single-term
constexpr int XA = 0;          // 2 bufs x 16KB (128 rows x 64 fp16, SW128)
constexpr int XW = 32768;      // 32KB fragment-direct W_ih (fp16, 64 cols x 256 k)
constexpr int SMEM_X = 65536;

// Scratch (__device__ globals: allocation-free)
__device__ float g_xproj[(size_t)TT * BB * GG];   // [t][b][g]
__device__ __half g_hhi[2][BB * HH];              // h (fp16), ping-pong
__device__ __half g_hlo[2][BB * HH];              // h lo correction (final step only)
__device__ __half g_xh[BB * TT * II];             // inputs fp16  [(b*T+t)][i]
__device__ __half g_wih[GG * II];                 // W_ih fp16 [g][i]
__device__ unsigned g_bar;                        // single step counter

// ---------------------------------------------------------------------------
// helpers
// ---------------------------------------------------------------------------
__device__ __forceinline__ uint32_t smem_u32(const void* p) {
    uint32_t a;
    asm("{ .reg .u64 t; cvta.to.shared.u64 t, %1; cvt.u32.u64 %0, t; }" : "=r"(a) : "l"(p));
    return a;
}
__device__ __forceinline__ void ldm_x4(uint32_t* r, uint32_t addr) {
    asm volatile("ldmatrix.sync.aligned.m8n8.x4.shared.b16 {%0,%1,%2,%3}, [%4];"
                 : "=r"(r[0]), "=r"(r[1]), "=r"(r[2]), "=r"(r[3]) : "r"(addr));
}
__device__ __forceinline__ void mma_f16(float* d, const uint32_t* a, uint32_t b0, uint32_t b1) {
    asm volatile(
        "mma.sync.aligned.m16n8k16.row.col.f32.f16.f16.f32 "
        "{%0,%1,%2,%3}, {%4,%5,%6,%7}, {%8,%9}, {%0,%1,%2,%3};"
        : "+f"(d[0]), "+f"(d[1]), "+f"(d[2]), "+f"(d[3])
        : "r"(a[0]), "r"(a[1]), "r"(a[2]), "r"(a[3]), "r"(b0), "r"(b1));
}
__device__ __forceinline__ uint32_t pack2h(__half a, __half b) {
    return (uint32_t)*(uint16_t*)&a | ((uint32_t)*(uint16_t*)&b << 16);
}
__device__ __forceinline__ float2 unpack2h(uint32_t v) {
    __half2 h = *(__half2*)&v;
    return __half22float2(h);
}
__device__ __forceinline__ void poll_ge(const unsigned* p, unsigned tgt) {
    unsigned v;
    do {
        asm volatile("ld.acquire.gpu.global.u32 %0, [%1];" : "=r"(v) : "l"(p) : "memory");
    } while (v < tgt);
}
// HW tanh: single MUFU op (sm_75+); sigmoid via tanh identity (1 MUFU + 1 FFMA)
__device__ __forceinline__ float ftanh(float x) {
    float y;
    asm("tanh.approx.f32 %0, %1;" : "=f"(y) : "f"(x));
    return y;
}
__device__ __forceinline__ float fsigmoid(float x) {
    return fmaf(ftanh(0.5f * x), 0.5f, 0.5f);
}

// ---------------------------------------------------------------------------
// Zero-init h buffers + step counter.
// ---------------------------------------------------------------------------
__global__ void zero_kernel() {
    int i = blockIdx.x * blockDim.x + threadIdx.x;
    if (i < BB * HH) {            // u32 words cover both ping-pong buffers
        ((unsigned*)g_hhi)[i] = 0u;
        ((unsigned*)g_hlo)[i] = 0u;
    }
    if (i == 0) g_bar = 0u;
}

// ---------------------------------------------------------------------------
// Convert inputs and W_ih to fp16 (row-major, same layout).
// ---------------------------------------------------------------------------
__global__ void conv_kernel(const float* __restrict__ inp, const float* __restrict__ Wih) {
    int stride = gridDim.x * blockDim.x;
    int i0 = blockIdx.x * blockDim.x + threadIdx.x;
    for (int i = i0; i < 1048576; i += stride) {       // inputs: 1M float4
        float4 v = ((const float4*)inp)[i];
        uint2 h = make_uint2(pack2h(__float2half(v.x), __float2half(v.y)),
                             pack2h(__float2half(v.z), __float2half(v.w)));
        ((uint2*)g_xh)[i] = h;
    }
    for (int i = i0; i < 262144; i += stride) {        // W_ih: 256K float4
        float4 v = ((const float4*)Wih)[i];
        uint2 h = make_uint2(pack2h(__float2half(v.x), __float2half(v.y)),
                             pack2h(__float2half(v.z), __float2half(v.w)));
        ((uint2*)g_wih)[i] = h;
    }
}

// ---------------------------------------------------------------------------
// x_proj via fp16 single-term mma.sync (proven round 9).
// ---------------------------------------------------------------------------
__global__ __launch_bounds__(256, 1) void xproj_mma_kernel(
    const float* __restrict__ bih, const float* __restrict__ bhh) {
    extern __shared__ char sm[];
    const int tid = threadIdx.x;
    const int lane = tid & 31;
    const int w = tid >> 5;
    const int n0 = blockIdx.x * 64;
    const uint32_t smb = smem_u32(sm);

    // W fragment fill (8192 u32, fp16)
    for (int idx = tid; idx < 8192; idx += 256) {
        int q = idx & 15, ln = (idx >> 4) & 31, ks = idx >> 9;
        int nt = q >> 1, rr = q & 1;
        int nl = nt * 8 + (ln >> 2);
        int k = ks * 16 + rr * 8 + (ln & 3) * 2;
        ((uint32_t*)(sm + XW))[idx] = *(const uint32_t*)(g_wih + (n0 + nl) * II + k);
    }
    __syncthreads();

    const int grp = lane >> 2, tg = lane & 3;
    float bias0[8], bias1[8];
#pragma unroll
    for (int nt = 0; nt < 8; nt++) {
        int g = n0 + nt * 8 + tg * 2;
        bias0[nt] = bih[g] + bhh[g];
        bias1[nt] = bih[g + 1] + bhh[g + 1];
    }

    const int arow = w * 16 + (lane & 15);
    const int acol = (lane >> 4) * 16;

    for (int miter = 0; miter < 8; miter++) {
        const int m0 = (blockIdx.y * 8 + miter) * 128;

        float acc[8][4];
#pragma unroll
        for (int z = 0; z < 8; z++)
#pragma unroll
            for (int r = 0; r < 4; r++) acc[z][r] = 0.f;

        // prologue: chunk 0 -> buf 0 (4 x 16B segments per thread)
#pragma unroll
        for (int i = 0; i < 4; i++) {
            int s = i * 256 + tid;
            int row = s >> 3, sb = s & 7;
            uint4 v = ((const uint4*)g_xh)[(m0 + row) * 32 + sb];
            int off = row * 128 + sb * 16;
            int sw = off ^ ((off >> 3) & 0x70);
            *(uint4*)(sm + XA + sw) = v;
        }
        __syncthreads();

        for (int ch = 0; ch < 4; ch++) {
            const int buf = ch & 1;
            uint4 ph[4];
            if (ch < 3) {
#pragma unroll
                for (int i = 0; i < 4; i++) {
                    int s = i * 256 + tid;
                    int row = s >> 3, sb = s & 7;
                    ph[i] = ((const uint4*)g_xh)[(m0 + row) * 32 + (ch + 1) * 8 + sb];
                }
            }
            const uint32_t ab = smb + XA + buf * 16384;
#pragma unroll
            for (int kl = 0; kl < 4; kl++) {
                const int ks = ch * 4 + kl;
                int off = arow * 128 + kl * 32 + acol;
                int sw = off ^ ((off >> 3) & 0x70);
                uint32_t ah[4];
                ldm_x4(ah, ab + sw);
                const uint4* wh4 = (const uint4*)(sm + XW) + (ks * 32 + lane) * 4;
#pragma unroll
                for (int q4 = 0; q4 < 4; q4++) {
                    uint4 bh = wh4[q4];
                    mma_f16(acc[2 * q4], ah, bh.x, bh.y);
                    mma_f16(acc[2 * q4 + 1], ah, bh.z, bh.w);
                }
            }
            if (ch < 3) {
                char* dh = sm + XA + (buf ^ 1) * 16384;
#pragma unroll
                for (int i = 0; i < 4; i++) {
                    int s = i * 256 + tid;
                    int row = s >> 3, sb = s & 7;
                    int off = row * 128 + sb * 16;
                    int sw = off ^ ((off >> 3) & 0x70);
                    *(uint4*)(dh + sw) = ph[i];
                }
            }
            __syncthreads();
        }

        int r0 = m0 + w * 16 + grp;
        int r1 = r0 + 8;
        size_t ob0 = ((size_t)(r0 & 255) * BB + (r0 >> 8)) * GG;
        size_t ob1 = ((size_t)(r1 & 255) * BB + (r1 >> 8)) * GG;
#pragma unroll
        for (int nt = 0; nt < 8; nt++) {
            int g = n0 + nt * 8 + tg * 2;
            float2 v0 = make_float2(acc[nt][0] + bias0[nt], acc[nt][1] + bias1[nt]);
            float2 v1 = make_float2(acc[nt][2] + bias0[nt], acc[nt][3] + bias1[nt]);
            *(float2*)&g_xproj[ob0 + g] = v0;
            *(float2*)&g_xproj[ob1 + g] = v1;
        }
    }
}

// ---------------------------------------------------------------------------
// Persistent LSTM recurrence: 128 CTAs x 256 thr, fp16 single-term.
// NEW warp tiling (r32, c32, kk256): warp w = (rg = w>>2, kh = w&3) owns
// rows [rg*32, rg*32+32) x all 32 gate-cols x k-chunk kh (256 k).
// Full h staged once into single-buffer SMEM; 4 k-partials reduced via
// exchange regions overlaid on the A buffer. LDSM+LDS wf halved vs R12.
// ---------------------------------------------------------------------------
__global__ __launch_bounds__(256, 1) void lstm_kernel(const float* __restrict__ Whh) {
    extern __shared__ char sm[];
    const int tid = threadIdx.x;
    const int lane = tid & 31;
    const int w = tid >> 5;
    const int rg = w >> 2, kh = w & 3;
    const int hc0 = blockIdx.x * 8;
    const uint32_t smb = smem_u32(sm);

    // ---- one-time: W fragment fill (fp16, fragment-direct layout) ----
    for (int idx = tid; idx < 16384; idx += 256) {
        int r = idx & 3, ln = (idx >> 2) & 31, ks = (idx >> 7) & 63, nhh = idx >> 13;
        int nt = r >> 1;
        int kk = (r & 1) * 8 + (ln & 3) * 2;
        int nl = nhh * 16 + nt * 8 + (ln >> 2);
        int k = ks * 16 + kk;
        int gr = (nl >> 3) * 1024 + hc0 + (nl & 7);
        __half h0 = __float2half(Whh[gr * 1024 + k]);
        __half h1 = __float2half(Whh[gr * 1024 + k + 1]);
        ((uint32_t*)(sm + WF))[idx] = pack2h(h0, h1);
    }
    __syncthreads();

    // xproj loader constants: thread loads (b=tid&63, q=tid>>6) 8 floats
    const int xlb = tid & 63, xlq = tid >> 6;
    const float* xsrc0 = g_xproj + (size_t)xlb * GG + xlq * HH + hc0;
    float* const xps = (float*)(sm + XP);

    // A ldmatrix per-lane constants: rows r0 = rg*32 + (lane&15), r1 = r0+16
    const int ar0 = rg * 32 + (lane & 15);
    const int ar1 = ar0 + 16;
    const int ahalf = lane >> 4;                // k-half within kstep

    // W fragment bases for this warp's chunk (uint4 idx = nh*2048 + ks*32 + lane)
    const uint4* wf0 = (const uint4*)(sm + WF) + (kh * 16) * 32 + lane;
    const uint4* wf1 = wf0 + 2048;

    // epilogue ownership: this thread handles states (b, ej) and (b, ej+4)
    const int eb = tid & 63, ej = tid >> 6;
    float c0 = 0.f, c1 = 0.f;

    for (int t = 0; t < TT; t++) {
        const uint4* gh = (const uint4*)g_hhi[t & 1];

        // stage this CTA's xproj slice (coalesced, h-independent): BEFORE poll
        {
            const float* src = xsrc0 + (size_t)t * BB * GG;
            float4 xv0 = *(const float4*)(src);
            float4 xv1 = *(const float4*)(src + 4);
            *(float4*)(xps + xlb * 36 + xlq * 8) = xv0;
            *(float4*)(xps + xlb * 36 + xlq * 8 + 4) = xv1;
        }

        // wait once for all CTAs to have finished step t-1
        if (t) {
            if (lane == 0) poll_ge(&g_bar, (unsigned)NCTA * t);
            __syncwarp();
        }

        // stage FULL h (8192 uint4) into A buffer, 32 uint4/thread, batches of 8
#pragma unroll
        for (int i0 = 0; i0 < 32; i0 += 8) {
            uint4 v[8];
#pragma unroll
            for (int i = 0; i < 8; i++) v[i] = __ldcg(gh + (i0 + i) * 256 + tid);
#pragma unroll
            for (int i = 0; i < 8; i++) {
                int s = (i0 + i) * 256 + tid;
                int row = s >> 7, seg = s & 127;
                int block = seg >> 3, inner = seg & 7;
                *(uint4*)(sm + A_B + row * 2048 + block * 128 + ((inner ^ (row & 7)) << 4)) = v[i];
            }
        }
        __syncthreads();

        // MMA: 16 ksteps of this warp's chunk; 8 independent chains
        float acc[8][4];
#pragma unroll
        for (int z = 0; z < 8; z++)
#pragma unroll
            for (int r = 0; r < 4; r++) acc[z][r] = 0.f;
#pragma unroll
        for (int kl = 0; kl < 16; kl++) {
            int seg = kh * 32 + kl * 2 + ahalf;
            int block = seg >> 3, inner = seg & 7;
            uint32_t a0[4], a1[4];
            ldm_x4(a0, smb + A_B + ar0 * 2048 + block * 128 + ((inner ^ (ar0 & 7)) << 4));
            ldm_x4(a1, smb + A_B + ar1 * 2048 + block * 128 + ((inner ^ (ar1 & 7)) << 4));
            uint4 b0 = wf0[kl * 32];
            uint4 b1 = wf1[kl * 32];
            mma_f16(acc[0], a0, b0.x, b0.y);
            mma_f16(acc[1], a0, b0.z, b0.w);
            mma_f16(acc[2], a0, b1.x, b1.y);
            mma_f16(acc[3], a0, b1.z, b1.w);
            mma_f16(acc[4], a1, b0.x, b0.y);
            mma_f16(acc[5], a1, b0.z, b0.w);
            mma_f16(acc[6], a1, b1.x, b1.y);
            mma_f16(acc[7], a1, b1.z, b1.w);
        }
        __syncthreads();   // A reads done -> safe to overlay exchange regions

        // epilogue: write partials to region kh  [32 cols][stride 72]
        {
            float* sgk = (float*)(sm + kh * 9216);
            int grp = lane >> 2, tg = lane & 3;
#pragma unroll
            for (int nj = 0; nj < 4; nj++) {
                int col = nj * 8 + tg * 2;
                int row0 = rg * 32 + grp;
                int row1 = row0 + 16;
                sgk[col * 72 + row0] = acc[nj][0];
                sgk[(col + 1) * 72 + row0] = acc[nj][1];
                sgk[col * 72 + row0 + 8] = acc[nj][2];
                sgk[(col + 1) * 72 + row0 + 8] = acc[nj][3];
                sgk[col * 72 + row1] = acc[4 + nj][0];
                sgk[(col + 1) * 72 + row1] = acc[4 + nj][1];
                sgk[col * 72 + row1 + 8] = acc[4 + nj][2];
                sgk[(col + 1) * 72 + row1 + 8] = acc[4 + nj][3];
            }
        }
        __syncthreads();

        // pointwise update (HW tanh): sum 4 k-partials; 2 states per thread
        {
            const float* s0 = (const float*)(sm);
            const float* s1 = (const float*)(sm + 9216);
            const float* s2 = (const float*)(sm + 18432);
            const float* s3 = (const float*)(sm + 27648);
            __half* hh = g_hhi[(t + 1) & 1];
            __half* hl = g_hlo[(t + 1) & 1];
            const bool last = (t == TT - 1);
            const float* xb = xps + eb * 36;
#pragma unroll
            for (int st = 0; st < 2; st++) {
                int j = ej + st * 4;
                int o0 = (0 + j) * 72 + eb, o1 = (8 + j) * 72 + eb;
                int o2 = (16 + j) * 72 + eb, o3 = (24 + j) * 72 + eb;
                float iv = s0[o0] + s1[o0] + s2[o0] + s3[o0] + xb[0 * 8 + j];
                float fv = s0[o1] + s1[o1] + s2[o1] + s3[o1] + xb[1 * 8 + j];
                float gv = s0[o2] + s1[o2] + s2[o2] + s3[o2] + xb[2 * 8 + j];
                float ov = s0[o3] + s1[o3] + s2[o3] + s3[o3] + xb[3 * 8 + j];
                float& cs = st ? c1 : c0;
                float cn = fsigmoid(fv) * cs + fsigmoid(iv) * ftanh(gv);
                cs = cn;
                float hn = fsigmoid(ov) * ftanh(cn);
                __half hbb = __float2half(hn);
                hh[eb * HH + hc0 + j] = hbb;
                if (last) hl[eb * HH + hc0 + j] = __float2half(hn - __half2float(hbb));
            }
        }
        __syncthreads();
        if (tid == 0) {
            __threadfence();                // order h stores (gpu scope)
            atomicAdd(&g_bar, 1u);          // signal this CTA's step done
        }
    }
}

// ---------------------------------------------------------------------------
// logits = h_last @ fc_w^T + fc_b; out = log_softmax.  grid=64, block=256.
// h_last = g_hhi[0] + g_hlo[0]  (full precision at the final step)
// ---------------------------------------------------------------------------
__global__ __launch_bounds__(256) void fc_kernel(const float* __restrict__ fcw,
                                                 const float* __restrict__ fcb,
                                                 float* __restrict__ out) {
    __shared__ float sh[HH];
    __shared__ float sl[64];
    __shared__ float s_red[2];
    int b = blockIdx.x;
    int tid = threadIdx.x;
    int w = tid >> 5, lane = tid & 31;

    {
        uint2 vh = ((const uint2*)(g_hhi[0] + b * HH))[tid];
        uint2 vl = ((const uint2*)(g_hlo[0] + b * HH))[tid];
        float2 h0 = unpack2h(vh.x), h1 = unpack2h(vh.y);
        float2 l0 = unpack2h(vl.x), l1 = unpack2h(vl.y);
        float4 f = make_float4(h0.x + l0.x, h0.y + l0.y, h1.x + l1.x, h1.y + l1.y);
        ((float4*)sh)[tid] = f;
    }
    __syncthreads();

#pragma unroll
    for (int cc = 0; cc < 8; cc++) {
        int c = w * 8 + cc;
        float s = 0.f;
        if (c < CC) {
            const float* wr = fcw + c * HH;
#pragma unroll 8
            for (int i = 0; i < 32; i++) {
                int k = i * 32 + lane;
                s += sh[k] * wr[k];
            }
        }
#pragma unroll
        for (int off = 16; off > 0; off >>= 1) s += __shfl_xor_sync(0xFFFFFFFF, s, off);
        if (lane == 0) sl[c] = (c < CC) ? s + fcb[c] : -1e30f;
    }
    __syncthreads();

    if (w == 0) {
        float v0 = sl[lane], v1 = sl[lane + 32];
        float m = fmaxf(v0, v1);
#pragma unroll
        for (int off = 16; off > 0; off >>= 1) m = fmaxf(m, __shfl_xor_sync(0xFFFFFFFF, m, off));
        float e = expf(v0 - m) + expf(v1 - m);
#pragma unroll
        for (int off = 16; off > 0; off >>= 1) e += __shfl_xor_sync(0xFFFFFFFF, e, off);
        if (lane == 0) { s_red[0] = m; s_red[1] = logf(e); }
    }
    __syncthreads();
    if (tid < CC) out[b * CC + tid] = sl[tid] - s_red[0] - s_red[1];
}

// ---------------------------------------------------------------------------
extern "C" void kernel_launch(void* const* d_in, const int* in_sizes, int n_in,
                              void* d_out, int out_size) {
    const float* inp = (const float*)d_in[0];   // [B,T,I]
    const float* Wih = (const float*)d_in[1];   // [4H,I]
    const float* Whh = (const float*)d_in[2];   // [4H,H]
    const float* bih = (const float*)d_in[3];   // [4H]
    const float* bhh = (const float*)d_in[4];   // [4H]
    const float* fcw = (const float*)d_in[5];   // [C,H]
    const float* fcb = (const float*)d_in[6];   // [C]
    float* out = (float*)d_out;                 // [B,C]

    cudaFuncSetAttribute(lstm_kernel, cudaFuncAttributeMaxDynamicSharedMemorySize, SMEM_DYN);
    cudaFuncSetAttribute(xproj_mma_kernel, cudaFuncAttributeMaxDynamicSharedMemorySize, SMEM_X);

    zero_kernel<<<512, 256>>>();
    conv_kernel<<<1024, 256>>>(inp, Wih);

    dim3 gx(64, 16);
    xproj_mma_kernel<<<gx, 256, SMEM_X>>>(bih, bhh);

    lstm_kernel<<<NCTA, 256, SMEM_DYN>>>(Whh);

    fc_kernel<<<BB, 64 * 4>>>(fcw, fcb, out);
}